// round 2
// baseline (speedup 1.0000x reference)
#include <cuda_runtime.h>
#include <cstdint>

#define HWSZ 268324
#define WD 518
#define NIMG 64
#define CAP 32768
#define EPSV 1e-8
#define CHSTRIDE 4193
#define BANDSZ 7252        // 14 rows * 518
#define NBANDS 37
#define L1W 259
#define L1SZ (259*259)

// ---------------- static device scratch ----------------
__device__ int g_mmode;
__device__ unsigned g_scnt[NIMG];
__device__ float g_sampP[NIMG][16384];
__device__ float g_sampY[NIMG][16384];
__device__ unsigned g_klo[128], g_khi[128];
__device__ int g_flag[128];
__device__ unsigned g_cnt[NIMG];
__device__ unsigned g_nb[128];
__device__ double g_sb[128];
__device__ double g_stot[128];
__device__ unsigned g_ccnt[128];
__device__ float g_cand[128][CAP];
__device__ float g_med[128], g_isc[128];
__device__ double g_rho[NIMG];
__device__ double g_gx[4], g_gy[4];
__device__ unsigned long long g_cx[4], g_cy[4];

__device__ float d1buf[NIMG * L1SZ];
__device__ unsigned char m1buf[NIMG * L1SZ];
__device__ float d2buf[NIMG * 129 * 129];
__device__ unsigned char m2buf[NIMG * 129 * 129];
__device__ float d3buf[NIMG * 64 * 64];
__device__ unsigned char m3buf[NIMG * 64 * 64];

// ---------------- helpers ----------------
__device__ __forceinline__ unsigned monot(float x) {
    unsigned u = __float_as_uint(x);
    return (u >> 31) ? ~u : (u | 0x80000000u);
}
__device__ __forceinline__ float inv_monot(unsigned k) {
    unsigned u = (k >> 31) ? (k & 0x7FFFFFFFu) : ~k;
    return __uint_as_float(u);
}

template <int MODE>
__device__ __forceinline__ bool maskAt(const void* m, int i) {
    if (MODE == 0) return ((const unsigned char*)m)[i] != 0;
    if (MODE == 2) return ((const int*)m)[i] != 0;
    return ((const float*)m)[i] != 0.f;
}
template <int MODE>
__device__ __forceinline__ void loadMask4(const void* m, int g4, bool& b0, bool& b1, bool& b2, bool& b3) {
    if (MODE == 0) { uchar4 v = ((const uchar4*)m)[g4]; b0 = v.x; b1 = v.y; b2 = v.z; b3 = v.w; }
    else if (MODE == 2) { int4 v = ((const int4*)m)[g4]; b0 = v.x != 0; b1 = v.y != 0; b2 = v.z != 0; b3 = v.w != 0; }
    else { float4 v = ((const float4*)m)[g4]; b0 = v.x != 0.f; b1 = v.y != 0.f; b2 = v.z != 0.f; b3 = v.w != 0.f; }
}

__device__ __forceinline__ double blockReduceD(double v, double* sh) {
    for (int o = 16; o; o >>= 1) v += __shfl_down_sync(0xffffffffu, v, o);
    int w = threadIdx.x >> 5, l = threadIdx.x & 31;
    if (l == 0) sh[w] = v;
    __syncthreads();
    double r = 0;
    if (threadIdx.x < 8) {
        r = sh[threadIdx.x];
        for (int o = 4; o; o >>= 1) r += __shfl_down_sync(0xffu, r, o);
    }
    return r;
}
__device__ __forceinline__ unsigned long long blockReduceU(unsigned long long v, unsigned long long* sh) {
    for (int o = 16; o; o >>= 1) v += __shfl_down_sync(0xffffffffu, v, o);
    int w = threadIdx.x >> 5, l = threadIdx.x & 31;
    if (l == 0) sh[w] = v;
    __syncthreads();
    unsigned long long r = 0;
    if (threadIdx.x < 8) {
        r = sh[threadIdx.x];
        for (int o = 4; o; o >>= 1) r += __shfl_down_sync(0xffu, r, o);
    }
    return r;
}

__device__ __forceinline__ void warpPush(bool d, float v, unsigned* ctr, float* arr) {
    unsigned b = __ballot_sync(0xffffffffu, d);
    if (!b) return;
    int lane = threadIdx.x & 31;
    unsigned pos = 0;
    int leader = __ffs(b) - 1;
    if (lane == leader) pos = atomicAdd(ctr, (unsigned)__popc(b));
    pos = __shfl_sync(0xffffffffu, pos, leader);
    if (d) {
        unsigned o = pos + __popc(b & ((1u << lane) - 1));
        if (o < CAP) arr[o] = v;
    }
}

// 4-bit radix select: k-th smallest (by monot key) of vals[0..n). Block-collective.
__device__ unsigned radixSelectG(const float* vals, int n, unsigned rank) {
    __shared__ unsigned cnts[8][16];
    __shared__ unsigned sPrefix, sRank;
    int tid = threadIdx.x, w = tid >> 5;
    if (tid == 0) { sPrefix = 0u; sRank = rank; }
    for (int shift = 28; shift >= 0; shift -= 4) {
        if (tid < 128) ((unsigned*)cnts)[tid] = 0u;
        __syncthreads();
        unsigned prefix = sPrefix;
        unsigned hiMask = (shift == 28) ? 0u : (0xFFFFFFFFu << (shift + 4));
        for (int i = tid; i < n; i += 256) {
            unsigned k = monot(vals[i]);
            if ((k & hiMask) == prefix) atomicAdd(&cnts[w][(k >> shift) & 15], 1u);
        }
        __syncthreads();
        if (tid == 0) {
            unsigned r = sRank, cum = 0;
            for (int d = 0; d < 16; d++) {
                unsigned c = 0;
                for (int ww = 0; ww < 8; ww++) c += cnts[ww][d];
                if (cum + c > r) { sPrefix = prefix | ((unsigned)d << shift); sRank = r - cum; break; }
                cum += c;
            }
        }
        __syncthreads();
    }
    return sPrefix;
}

// ---------------- kernels ----------------
__global__ void k_init(const void* mask) {
    int tid = threadIdx.x;
    for (int i = tid; i < NIMG; i += 256) { g_scnt[i] = 0u; g_cnt[i] = 0u; g_rho[i] = 0.0; }
    for (int i = tid; i < 128; i += 256) {
        g_nb[i] = 0u; g_sb[i] = 0.0; g_stot[i] = 0.0; g_ccnt[i] = 0u; g_flag[i] = 0;
    }
    if (tid < 4) { g_gx[tid] = 0.0; g_gy[tid] = 0.0; g_cx[tid] = 0ull; g_cy[tid] = 0ull; }
    if (tid == 0) {
        const unsigned char* b = (const unsigned char*)mask;
        bool nonbin = false, offnz = false;
        for (int j = 0; j < 256; j++) {
            unsigned char v = b[j];
            if (v > 1) nonbin = true;
            if ((j & 3) && v) offnz = true;
        }
        g_mmode = nonbin ? 1 : (offnz ? 0 : 2);
    }
}

template <int MODE>
__device__ __forceinline__ void sample_impl(const float* P, const float* Y, const void* M) {
    int img = blockIdx.y, tid = threadIdx.x;
    for (int ch = blockIdx.x * 8; ch < blockIdx.x * 8 + 8; ch++) {
        int idx = img * HWSZ + ch * CHSTRIDE + tid;
        bool v = maskAt<MODE>(M, idx);
        float p = P[idx], q = Y[idx];
        unsigned b = __ballot_sync(0xffffffffu, v);
        if (b) {
            int lane = tid & 31;
            unsigned pos = 0;
            int leader = __ffs(b) - 1;
            if (lane == leader) pos = atomicAdd(&g_scnt[img], (unsigned)__popc(b));
            pos = __shfl_sync(0xffffffffu, pos, leader);
            if (v) {
                unsigned o = pos + __popc(b & ((1u << lane) - 1));
                g_sampP[img][o] = p;
                g_sampY[img][o] = q;
            }
        }
    }
}
__global__ void __launch_bounds__(256) k_sample(const float* P, const float* Y, const void* M) {
    int m = g_mmode;
    if (m == 0) sample_impl<0>(P, Y, M);
    else if (m == 2) sample_impl<2>(P, Y, M);
    else sample_impl<1>(P, Y, M);
}

__global__ void __launch_bounds__(256) k_smed() {
    int t = blockIdx.x, img = t >> 1;
    int n = (int)g_scnt[img];
    if (n == 0) { if (threadIdx.x == 0) { g_flag[t] = 1; g_klo[t] = 0u; g_khi[t] = 0u; } return; }
    const float* src = (t & 1) ? g_sampY[img] : g_sampP[img];
    unsigned r50 = (unsigned)((n - 1) >> 1);
    unsigned r45 = (unsigned)((45LL * (n - 1)) / 100);
    unsigned r55 = (unsigned)((55LL * (n - 1)) / 100);
    unsigned k45 = radixSelectG(src, n, r45);
    unsigned k50 = radixSelectG(src, n, r50);
    unsigned k55 = radixSelectG(src, n, r55);
    if (threadIdx.x == 0) {
        float q45 = inv_monot(k45), q50 = inv_monot(k50), q55 = inv_monot(k55);
        float delta = 0.45f * (q55 - q45);
        g_klo[t] = monot(q50 - delta);
        g_khi[t] = monot(q50 + delta);
    }
}

template <int MODE>
__device__ __forceinline__ void scan_impl(const float* P, const float* Y, const void* M) {
    __shared__ double redD[8];
    __shared__ unsigned long long redU[8];
    int img = blockIdx.y, tid = threadIdx.x;
    const int PER = 8388;
    int s = blockIdx.x * PER;
    int e = min(s + PER, HWSZ);
    int nv = (e - s) >> 2;
    int iters = (nv + 255) >> 8;
    int base4 = img * (HWSZ / 4) + (s >> 2);
    unsigned kloP = g_klo[2 * img], khiP = g_khi[2 * img];
    unsigned kloY = g_klo[2 * img + 1], khiY = g_khi[2 * img + 1];
    const float4* P4 = (const float4*)P;
    const float4* Y4 = (const float4*)Y;
    unsigned* ctrP = &g_ccnt[2 * img];
    unsigned* ctrY = &g_ccnt[2 * img + 1];
    float* candP = g_cand[2 * img];
    float* candY = g_cand[2 * img + 1];
    unsigned cnt = 0, nbP = 0, nbY = 0;
    double sbP = 0, sbY = 0, stP = 0, stY = 0;
    for (int it = 0; it < iters; it++) {
        int v4 = it * 256 + tid;
        bool ok = v4 < nv;
        int gi = ok ? (base4 + v4) : base4;
        float4 p = P4[gi], q = Y4[gi];
        bool mv[4];
        loadMask4<MODE>(M, gi, mv[0], mv[1], mv[2], mv[3]);
        float pv[4] = {p.x, p.y, p.z, p.w};
        float qv[4] = {q.x, q.y, q.z, q.w};
#pragma unroll
        for (int j = 0; j < 4; j++) {
            bool m = ok && mv[j];
            bool pushP = false, pushY = false;
            if (m) {
                cnt++;
                float a = pv[j];
                unsigned kp = monot(a);
                stP += a;
                if (kp < kloP) { nbP++; sbP += a; }
                else if (kp <= khiP) pushP = true;
                float b = qv[j];
                unsigned ky = monot(b);
                stY += b;
                if (ky < kloY) { nbY++; sbY += b; }
                else if (ky <= khiY) pushY = true;
            }
            warpPush(pushP, pv[j], ctrP, candP);
            warpPush(pushY, qv[j], ctrY, candY);
        }
    }
    double r;
    r = blockReduceD(sbP, redD); if (tid == 0) atomicAdd(&g_sb[2 * img], r); __syncthreads();
    r = blockReduceD(sbY, redD); if (tid == 0) atomicAdd(&g_sb[2 * img + 1], r); __syncthreads();
    r = blockReduceD(stP, redD); if (tid == 0) atomicAdd(&g_stot[2 * img], r); __syncthreads();
    r = blockReduceD(stY, redD); if (tid == 0) atomicAdd(&g_stot[2 * img + 1], r); __syncthreads();
    unsigned long long u;
    u = blockReduceU(cnt, redU); if (tid == 0) atomicAdd(&g_cnt[img], (unsigned)u); __syncthreads();
    u = blockReduceU(nbP, redU); if (tid == 0) atomicAdd(&g_nb[2 * img], (unsigned)u); __syncthreads();
    u = blockReduceU(nbY, redU); if (tid == 0) atomicAdd(&g_nb[2 * img + 1], (unsigned)u);
}
__global__ void __launch_bounds__(256) k_scan(const float* P, const float* Y, const void* M) {
    int m = g_mmode;
    if (m == 0) scan_impl<0>(P, Y, M);
    else if (m == 2) scan_impl<2>(P, Y, M);
    else scan_impl<1>(P, Y, M);
}

__global__ void __launch_bounds__(256) k_select() {
    int t = blockIdx.x, img = t >> 1, tid = threadIdx.x;
    __shared__ double redD[8];
    __shared__ unsigned long long redU[8];
    unsigned cnt = g_cnt[img];
    if (cnt == 0) { if (tid == 0) { g_med[t] = 0.f; g_isc[t] = (float)(1.0 / EPSV); g_flag[t] = 0; } return; }
    if (g_flag[t]) return;  // sample failure -> fallback
    unsigned r = (cnt - 1) >> 1;
    unsigned nb_lo = g_nb[t];
    unsigned ncand = g_ccnt[t];
    long long j = (long long)r - (long long)nb_lo;
    if (ncand > CAP || j < 0 || j >= (long long)ncand) { if (tid == 0) g_flag[t] = 1; return; }
    unsigned mkey = radixSelectG(g_cand[t], (int)ncand, (unsigned)j);
    unsigned nl = 0;
    double sl = 0;
    for (int i = tid; i < (int)ncand; i += 256) {
        float v = g_cand[t][i];
        if (monot(v) < mkey) { nl++; sl += (double)v; }
    }
    double sls = blockReduceD(sl, redD);
    __syncthreads();
    unsigned long long nls = blockReduceU(nl, redU);
    if (tid == 0) {
        double med = (double)inv_monot(mkey);
        double nb = (double)nb_lo + (double)nls;
        double Sb = g_sb[t] + sls;
        double abs_sum = g_stot[t] - 2.0 * Sb + med * (2.0 * nb - (double)cnt);
        if (abs_sum < 0.0) abs_sum = 0.0;
        double sc = abs_sum / (double)cnt + EPSV;
        g_med[t] = (float)med;
        g_isc[t] = (float)(1.0 / sc);
    }
}

// Exact fallback (normally all blocks return immediately).
__global__ void __launch_bounds__(256) k_fallback(const float* P, const float* Y, const void* M) {
    int t = blockIdx.x;
    if (g_flag[t] == 0) return;
    int img = t >> 1, tid = threadIdx.x;
    unsigned cnt = g_cnt[img];
    if (cnt == 0) { if (tid == 0) { g_med[t] = 0.f; g_isc[t] = (float)(1.0 / EPSV); } return; }
    const float* src = (t & 1) ? Y : P;
    int mode = g_mmode;
    int base = img * HWSZ;
    unsigned r = (cnt - 1) >> 1;
    __shared__ unsigned sTot;
    __shared__ double sD;
    unsigned key = 0;
    for (int bit = 31; bit >= 0; bit--) {
        unsigned pivot = key | (1u << bit);
        if (tid == 0) sTot = 0u;
        __syncthreads();
        unsigned c = 0;
        for (int i = tid; i < HWSZ; i += 256) {
            bool m = (mode == 0) ? ((const unsigned char*)M)[base + i] != 0
                   : (mode == 2) ? ((const int*)M)[base + i] != 0
                   : ((const float*)M)[base + i] != 0.f;
            if (m && monot(src[base + i]) < pivot) c++;
        }
        for (int o = 16; o; o >>= 1) c += __shfl_down_sync(0xffffffffu, c, o);
        if ((tid & 31) == 0) atomicAdd(&sTot, c);
        __syncthreads();
        if (sTot <= r) key = pivot;
        __syncthreads();
    }
    if (tid == 0) { sTot = 0u; sD = 0.0; }
    __syncthreads();
    unsigned nb = 0;
    double Sb = 0;
    for (int i = tid; i < HWSZ; i += 256) {
        bool m = (mode == 0) ? ((const unsigned char*)M)[base + i] != 0
               : (mode == 2) ? ((const int*)M)[base + i] != 0
               : ((const float*)M)[base + i] != 0.f;
        if (m) {
            float v = src[base + i];
            if (monot(v) < key) { nb++; Sb += (double)v; }
        }
    }
    for (int o = 16; o; o >>= 1) { nb += __shfl_down_sync(0xffffffffu, nb, o); Sb += __shfl_down_sync(0xffffffffu, Sb, o); }
    if ((tid & 31) == 0) { atomicAdd(&sTot, nb); atomicAdd(&sD, Sb); }
    __syncthreads();
    if (tid == 0) {
        double med = (double)inv_monot(key);
        double abs_sum = g_stot[t] - 2.0 * sD + med * (2.0 * (double)sTot - (double)cnt);
        if (abs_sum < 0.0) abs_sum = 0.0;
        double sc = abs_sum / (double)cnt + EPSV;
        g_med[t] = (float)med;
        g_isc[t] = (float)(1.0 / sc);
    }
}

template <int MODE>
__device__ __forceinline__ void main_impl(const float* P, const float* Y, const void* M) {
    __shared__ float sd[BANDSZ + WD + 2];
    __shared__ unsigned char sm[BANDSZ + WD + 2];
    __shared__ double redD[8];
    __shared__ unsigned long long redU[8];
    int img = blockIdx.y, band = blockIdx.x, tid = threadIdx.x;
    bool last = (band == NBANDS - 1);
    int nelem = last ? BANDSZ : (BANDSZ + WD);   // 7252 or 7770
    float medp = g_med[2 * img], medy = g_med[2 * img + 1];
    float iscp = g_isc[2 * img], iscy = g_isc[2 * img + 1];
    int ebase = img * HWSZ + band * BANDSZ;
    int base4 = ebase >> 2;
    int nv = (nelem & ~3) >> 2;                  // 1813 or 1942
    const float4* P4 = (const float4*)P;
    const float4* Y4 = (const float4*)Y;
    for (int v = tid; v < nv; v += 256) {
        float4 p = P4[base4 + v];
        float4 q = Y4[base4 + v];
        bool m0, m1, m2, m3;
        loadMask4<MODE>(M, base4 + v, m0, m1, m2, m3);
        int o = v * 4;
        sd[o]     = (p.x - medp) * iscp - (q.x - medy) * iscy; sm[o]     = m0;
        sd[o + 1] = (p.y - medp) * iscp - (q.y - medy) * iscy; sm[o + 1] = m1;
        sd[o + 2] = (p.z - medp) * iscp - (q.z - medy) * iscy; sm[o + 2] = m2;
        sd[o + 3] = (p.w - medp) * iscp - (q.w - medy) * iscy; sm[o + 3] = m3;
    }
    if (!last && tid < 2) {   // 7770 = 1942*4 + 2 leftover
        int o = 7768 + tid;
        int gi = ebase + o;
        float p = P[gi], q = Y[gi];
        sd[o] = (p - medp) * iscp - (q - medy) * iscy;
        sm[o] = maskAt<MODE>(M, gi) ? 1 : 0;
    }
    __syncthreads();
    float rho = 0.f, gx = 0.f, gy = 0.f;
    unsigned cx = 0, cy = 0;
    int npair = last ? (13 * WD) : BANDSZ;
    for (int i = tid; i < BANDSZ; i += 256) {
        int c = i - (i / WD) * WD;
        unsigned char m = sm[i];
        float d = sd[i];
        if (m) {
            rho += fabsf(d);
            if (c < WD - 1 && sm[i + 1]) { gx += fabsf(sd[i + 1] - d); cx++; }
            if (i < npair && sm[i + WD]) { gy += fabsf(sd[i + WD] - d); cy++; }
        }
    }
    // 2x2 pool -> level 1 (7 pooled rows x 259)
    float* d1 = d1buf + img * L1SZ + band * 7 * L1W;
    unsigned char* m1 = m1buf + img * L1SZ + band * 7 * L1W;
    for (int i = tid; i < 7 * L1W; i += 256) {
        int pr = i / L1W, pc = i - pr * L1W;
        int o0 = (2 * pr) * WD + 2 * pc;
        d1[i] = 0.25f * (sd[o0] + sd[o0 + 1] + sd[o0 + WD] + sd[o0 + WD + 1]);
        m1[i] = sm[o0] | sm[o0 + 1] | sm[o0 + WD] | sm[o0 + WD + 1];
    }
    double r1 = blockReduceD((double)rho, redD); __syncthreads();
    double r2 = blockReduceD((double)gx, redD);  __syncthreads();
    double r3 = blockReduceD((double)gy, redD);  __syncthreads();
    unsigned long long u1 = blockReduceU(cx, redU); __syncthreads();
    unsigned long long u2 = blockReduceU(cy, redU);
    if (tid == 0) {
        atomicAdd(&g_rho[img], r1);
        atomicAdd(&g_gx[0], r2); atomicAdd(&g_gy[0], r3);
        atomicAdd(&g_cx[0], u1); atomicAdd(&g_cy[0], u2);
    }
}
__global__ void __launch_bounds__(256) k_main(const float* P, const float* Y, const void* M) {
    int m = g_mmode;
    if (m == 0) main_impl<0>(P, Y, M);
    else if (m == 2) main_impl<2>(P, Y, M);
    else main_impl<1>(P, Y, M);
}

__global__ void __launch_bounds__(256) k_grad(int lvl) {
    const float* d; const unsigned char* m; int Hc, Wc;
    if (lvl == 1) { d = d1buf; m = m1buf; Hc = 259; Wc = 259; }
    else if (lvl == 2) { d = d2buf; m = m2buf; Hc = 129; Wc = 129; }
    else { d = d3buf; m = m3buf; Hc = 64; Wc = 64; }
    __shared__ double redD[8];
    __shared__ unsigned long long redU[8];
    int per = Hc * Wc, total = NIMG * per;
    double gx = 0, gy = 0;
    unsigned cx = 0, cy = 0;
    for (int i = blockIdx.x * blockDim.x + threadIdx.x; i < total; i += gridDim.x * blockDim.x) {
        if (!m[i]) continue;
        int rem = i % per;
        int r = rem / Wc, c = rem - r * Wc;
        float dv = d[i];
        if (c < Wc - 1 && m[i + 1]) { gx += (double)fabsf(d[i + 1] - dv); cx++; }
        if (r < Hc - 1 && m[i + Wc]) { gy += (double)fabsf(d[i + Wc] - dv); cy++; }
    }
    double r2 = blockReduceD(gx, redD); __syncthreads();
    double r3 = blockReduceD(gy, redD); __syncthreads();
    unsigned long long u1 = blockReduceU(cx, redU); __syncthreads();
    unsigned long long u2 = blockReduceU(cy, redU);
    if (threadIdx.x == 0) {
        atomicAdd(&g_gx[lvl], r2); atomicAdd(&g_gy[lvl], r3);
        atomicAdd(&g_cx[lvl], u1); atomicAdd(&g_cy[lvl], u2);
    }
}

__global__ void __launch_bounds__(256) k_pool(int lvl) {
    const float* din; const unsigned char* mi; float* dout; unsigned char* mo;
    int Hi, Wi, Ho, Wo;
    if (lvl == 1) { din = d1buf; mi = m1buf; dout = d2buf; mo = m2buf; Hi = 259; Wi = 259; Ho = 129; Wo = 129; }
    else { din = d2buf; mi = m2buf; dout = d3buf; mo = m3buf; Hi = 129; Wi = 129; Ho = 64; Wo = 64; }
    int per = Ho * Wo, total = NIMG * per;
    for (int i = blockIdx.x * blockDim.x + threadIdx.x; i < total; i += gridDim.x * blockDim.x) {
        int img = i / per, rem = i - img * per;
        int r = rem / Wo, c = rem - r * Wo;
        int bi = img * Hi * Wi + (2 * r) * Wi + 2 * c;
        dout[i] = 0.25f * (din[bi] + din[bi + 1] + din[bi + Wi] + din[bi + Wi + 1]);
        mo[i] = mi[bi] | mi[bi + 1] | mi[bi + Wi] | mi[bi + Wi + 1];
    }
}

__global__ void k_final(float* out) {
    if (threadIdx.x == 0 && blockIdx.x == 0) {
        double ssi = 0;
        for (int i = 0; i < NIMG; i++) {
            double v = (double)g_cnt[i];
            if (v < 1.0) v = 1.0;
            ssi += g_rho[i] / v;
        }
        ssi /= (double)NIMG;
        double g = 0;
        for (int s = 0; s < 4; s++) {
            double cx = (double)g_cx[s]; if (cx < 1.0) cx = 1.0;
            double cy = (double)g_cy[s]; if (cy < 1.0) cy = 1.0;
            g += g_gx[s] / cx + g_gy[s] / cy;
        }
        out[0] = (float)(ssi + 0.5 * (g / 4.0));
    }
}

extern "C" void kernel_launch(void* const* d_in, const int* in_sizes, int n_in,
                              void* d_out, int out_size) {
    const float* pred = (const float*)d_in[0];
    const float* yv = (const float*)d_in[1];
    const void* mask = d_in[2];
    float* out = (float*)d_out;

    k_init<<<1, 256>>>(mask);
    k_sample<<<dim3(8, NIMG), 256>>>(pred, yv, mask);
    k_smed<<<128, 256>>>();
    k_scan<<<dim3(32, NIMG), 256>>>(pred, yv, mask);
    k_select<<<128, 256>>>();
    k_fallback<<<128, 256>>>(pred, yv, mask);
    k_main<<<dim3(NBANDS, NIMG), 256>>>(pred, yv, mask);
    k_grad<<<2048, 256>>>(1);
    k_pool<<<1024, 256>>>(1);
    k_grad<<<1024, 256>>>(2);
    k_pool<<<512, 256>>>(2);
    k_grad<<<512, 256>>>(3);
    k_final<<<1, 32>>>(out);
}

// round 3
// speedup vs baseline: 1.4500x; 1.4500x over previous
#include <cuda_runtime.h>
#include <cstdint>

#define HWSZ 268324
#define WD 518
#define NIMG 64
#define CAP 32768
#define SCAP 2048
#define EPSV 1e-8
#define CHSTRIDE 4193
#define BANDSZ 7252        // 14 rows * 518
#define NBANDS 37
#define L1W 259
#define L1SZ (259*259)

// ---------------- static device scratch ----------------
__device__ int g_mmode;
__device__ unsigned g_scnt[NIMG];
__device__ float g_sampP[NIMG][16384];
__device__ float g_sampY[NIMG][16384];
__device__ unsigned g_klo[128], g_khi[128];
__device__ int g_flag[128];
__device__ unsigned g_cnt[NIMG];
__device__ unsigned g_nb[128];
__device__ double g_sb[128];
__device__ double g_stot[128];
__device__ unsigned g_ccnt[128];
__device__ float g_cand[128][CAP];
__device__ float g_med[128], g_isc[128];
__device__ double g_rho[NIMG];
__device__ double g_gx[4], g_gy[4];
__device__ unsigned long long g_cx[4], g_cy[4];

__device__ float d1buf[NIMG * L1SZ];
__device__ unsigned char m1buf[NIMG * L1SZ];
__device__ float d2buf[NIMG * 129 * 129];
__device__ unsigned char m2buf[NIMG * 129 * 129];
__device__ float d3buf[NIMG * 64 * 64];
__device__ unsigned char m3buf[NIMG * 64 * 64];

// ---------------- helpers ----------------
__device__ __forceinline__ unsigned monot(float x) {
    unsigned u = __float_as_uint(x);
    return (u >> 31) ? ~u : (u | 0x80000000u);
}
__device__ __forceinline__ float inv_monot(unsigned k) {
    unsigned u = (k >> 31) ? (k & 0x7FFFFFFFu) : ~k;
    return __uint_as_float(u);
}

template <int MODE>
__device__ __forceinline__ bool maskAt(const void* m, int i) {
    if (MODE == 0) return ((const unsigned char*)m)[i] != 0;
    if (MODE == 2) return ((const int*)m)[i] != 0;
    return ((const float*)m)[i] != 0.f;
}
template <int MODE>
__device__ __forceinline__ void loadMask4(const void* m, int g4, bool& b0, bool& b1, bool& b2, bool& b3) {
    if (MODE == 0) { uchar4 v = ((const uchar4*)m)[g4]; b0 = v.x; b1 = v.y; b2 = v.z; b3 = v.w; }
    else if (MODE == 2) { int4 v = ((const int4*)m)[g4]; b0 = v.x != 0; b1 = v.y != 0; b2 = v.z != 0; b3 = v.w != 0; }
    else { float4 v = ((const float4*)m)[g4]; b0 = v.x != 0.f; b1 = v.y != 0.f; b2 = v.z != 0.f; b3 = v.w != 0.f; }
}

__device__ __forceinline__ double blockReduceD(double v, double* sh) {
    for (int o = 16; o; o >>= 1) v += __shfl_down_sync(0xffffffffu, v, o);
    int w = threadIdx.x >> 5, l = threadIdx.x & 31;
    if (l == 0) sh[w] = v;
    __syncthreads();
    double r = 0;
    if (threadIdx.x < 8) {
        r = sh[threadIdx.x];
        for (int o = 4; o; o >>= 1) r += __shfl_down_sync(0xffu, r, o);
    }
    return r;
}
__device__ __forceinline__ unsigned long long blockReduceU(unsigned long long v, unsigned long long* sh) {
    for (int o = 16; o; o >>= 1) v += __shfl_down_sync(0xffffffffu, v, o);
    int w = threadIdx.x >> 5, l = threadIdx.x & 31;
    if (l == 0) sh[w] = v;
    __syncthreads();
    unsigned long long r = 0;
    if (threadIdx.x < 8) {
        r = sh[threadIdx.x];
        for (int o = 4; o; o >>= 1) r += __shfl_down_sync(0xffu, r, o);
    }
    return r;
}

// Warp-aggregated push into a SHARED-memory staging buffer (cheap smem atomic).
__device__ __forceinline__ void warpPushS(bool d, float v, unsigned* ctr, float* arr) {
    unsigned b = __ballot_sync(0xffffffffu, d);
    if (!b) return;
    int lane = threadIdx.x & 31;
    unsigned pos = 0;
    int leader = __ffs(b) - 1;
    if (lane == leader) pos = atomicAdd(ctr, (unsigned)__popc(b));
    pos = __shfl_sync(0xffffffffu, pos, leader);
    if (d) {
        unsigned o = pos + __popc(b & ((1u << lane) - 1));
        if (o < SCAP) arr[o] = v;
    }
}

// 4-bit radix select: k-th smallest (by monot key) of vals[0..n). Block-collective.
__device__ unsigned radixSelectG(const float* vals, int n, unsigned rank) {
    __shared__ unsigned cnts[8][16];
    __shared__ unsigned sPrefix, sRank;
    int tid = threadIdx.x, w = tid >> 5;
    if (tid == 0) { sPrefix = 0u; sRank = rank; }
    for (int shift = 28; shift >= 0; shift -= 4) {
        if (tid < 128) ((unsigned*)cnts)[tid] = 0u;
        __syncthreads();
        unsigned prefix = sPrefix;
        unsigned hiMask = (shift == 28) ? 0u : (0xFFFFFFFFu << (shift + 4));
        for (int i = tid; i < n; i += 256) {
            unsigned k = monot(vals[i]);
            if ((k & hiMask) == prefix) atomicAdd(&cnts[w][(k >> shift) & 15], 1u);
        }
        __syncthreads();
        if (tid == 0) {
            unsigned r = sRank, cum = 0;
            for (int d = 0; d < 16; d++) {
                unsigned c = 0;
                for (int ww = 0; ww < 8; ww++) c += cnts[ww][d];
                if (cum + c > r) { sPrefix = prefix | ((unsigned)d << shift); sRank = r - cum; break; }
                cum += c;
            }
        }
        __syncthreads();
    }
    return sPrefix;
}

// ---------------- kernels ----------------
__global__ void k_init(const void* mask) {
    int tid = threadIdx.x;
    for (int i = tid; i < NIMG; i += 256) { g_scnt[i] = 0u; g_cnt[i] = 0u; g_rho[i] = 0.0; }
    for (int i = tid; i < 128; i += 256) {
        g_nb[i] = 0u; g_sb[i] = 0.0; g_stot[i] = 0.0; g_ccnt[i] = 0u; g_flag[i] = 0;
    }
    if (tid < 4) { g_gx[tid] = 0.0; g_gy[tid] = 0.0; g_cx[tid] = 0ull; g_cy[tid] = 0ull; }
    if (tid == 0) {
        const unsigned char* b = (const unsigned char*)mask;
        bool nonbin = false, offnz = false;
        for (int j = 0; j < 256; j++) {
            unsigned char v = b[j];
            if (v > 1) nonbin = true;
            if ((j & 3) && v) offnz = true;
        }
        g_mmode = nonbin ? 1 : (offnz ? 0 : 2);
    }
}

template <int MODE>
__device__ __forceinline__ void sample_impl(const float* P, const float* Y, const void* M) {
    int img = blockIdx.y, tid = threadIdx.x;
    for (int ch = blockIdx.x * 8; ch < blockIdx.x * 8 + 8; ch++) {
        int idx = img * HWSZ + ch * CHSTRIDE + tid;
        bool v = maskAt<MODE>(M, idx);
        float p = P[idx], q = Y[idx];
        unsigned b = __ballot_sync(0xffffffffu, v);
        if (b) {
            int lane = tid & 31;
            unsigned pos = 0;
            int leader = __ffs(b) - 1;
            if (lane == leader) pos = atomicAdd(&g_scnt[img], (unsigned)__popc(b));
            pos = __shfl_sync(0xffffffffu, pos, leader);
            if (v) {
                unsigned o = pos + __popc(b & ((1u << lane) - 1));
                g_sampP[img][o] = p;
                g_sampY[img][o] = q;
            }
        }
    }
}
__global__ void __launch_bounds__(256) k_sample(const float* P, const float* Y, const void* M) {
    int m = g_mmode;
    if (m == 0) sample_impl<0>(P, Y, M);
    else if (m == 2) sample_impl<2>(P, Y, M);
    else sample_impl<1>(P, Y, M);
}

__global__ void __launch_bounds__(256) k_smed() {
    int t = blockIdx.x, img = t >> 1;
    int n = (int)g_scnt[img];
    if (n == 0) { if (threadIdx.x == 0) { g_flag[t] = 1; g_klo[t] = 0u; g_khi[t] = 0u; } return; }
    const float* src = (t & 1) ? g_sampY[img] : g_sampP[img];
    unsigned r50 = (unsigned)((n - 1) >> 1);
    unsigned r45 = (unsigned)((45LL * (n - 1)) / 100);
    unsigned r55 = (unsigned)((55LL * (n - 1)) / 100);
    unsigned k45 = radixSelectG(src, n, r45);
    unsigned k50 = radixSelectG(src, n, r50);
    unsigned k55 = radixSelectG(src, n, r55);
    if (threadIdx.x == 0) {
        float q45 = inv_monot(k45), q50 = inv_monot(k50), q55 = inv_monot(k55);
        float delta = 0.45f * (q55 - q45);
        g_klo[t] = monot(q50 - delta);
        g_khi[t] = monot(q50 + delta);
    }
}

template <int MODE>
__device__ __forceinline__ void scan_impl(const float* P, const float* Y, const void* M) {
    __shared__ float sCP[SCAP], sCY[SCAP];
    __shared__ unsigned sNP, sNY, sBP, sBY;
    __shared__ double redD[8];
    __shared__ unsigned long long redU[8];
    int img = blockIdx.y, tid = threadIdx.x;
    if (tid == 0) { sNP = 0u; sNY = 0u; }
    __syncthreads();
    const int PER = 8388;
    int s = blockIdx.x * PER;
    int e = min(s + PER, HWSZ);
    int nv = (e - s) >> 2;
    int iters = (nv + 255) >> 8;
    int base4 = img * (HWSZ / 4) + (s >> 2);
    unsigned kloP = g_klo[2 * img], khiP = g_khi[2 * img];
    unsigned kloY = g_klo[2 * img + 1], khiY = g_khi[2 * img + 1];
    const float4* P4 = (const float4*)P;
    const float4* Y4 = (const float4*)Y;
    unsigned cnt = 0, nbP = 0, nbY = 0;
    double sbP = 0, sbY = 0, stP = 0, stY = 0;
    for (int it = 0; it < iters; it++) {
        int v4 = it * 256 + tid;
        bool ok = v4 < nv;
        int gi = ok ? (base4 + v4) : base4;
        float4 p = P4[gi], q = Y4[gi];
        bool mv[4];
        loadMask4<MODE>(M, gi, mv[0], mv[1], mv[2], mv[3]);
        float pv[4] = {p.x, p.y, p.z, p.w};
        float qv[4] = {q.x, q.y, q.z, q.w};
#pragma unroll
        for (int j = 0; j < 4; j++) {
            bool m = ok && mv[j];
            bool pushP = false, pushY = false;
            if (m) {
                cnt++;
                float a = pv[j];
                unsigned kp = monot(a);
                stP += a;
                if (kp < kloP) { nbP++; sbP += a; }
                else if (kp <= khiP) pushP = true;
                float b = qv[j];
                unsigned ky = monot(b);
                stY += b;
                if (ky < kloY) { nbY++; sbY += b; }
                else if (ky <= khiY) pushY = true;
            }
            warpPushS(pushP, pv[j], &sNP, sCP);
            warpPushS(pushY, qv[j], &sNY, sCY);
        }
    }
    double r;
    r = blockReduceD(sbP, redD); if (tid == 0) atomicAdd(&g_sb[2 * img], r); __syncthreads();
    r = blockReduceD(sbY, redD); if (tid == 0) atomicAdd(&g_sb[2 * img + 1], r); __syncthreads();
    r = blockReduceD(stP, redD); if (tid == 0) atomicAdd(&g_stot[2 * img], r); __syncthreads();
    r = blockReduceD(stY, redD); if (tid == 0) atomicAdd(&g_stot[2 * img + 1], r); __syncthreads();
    unsigned long long u;
    u = blockReduceU(cnt, redU); if (tid == 0) atomicAdd(&g_cnt[img], (unsigned)u); __syncthreads();
    u = blockReduceU(nbP, redU); if (tid == 0) atomicAdd(&g_nb[2 * img], (unsigned)u); __syncthreads();
    u = blockReduceU(nbY, redU); if (tid == 0) atomicAdd(&g_nb[2 * img + 1], (unsigned)u);
    __syncthreads();
    // One global reservation per block per tensor, then bulk copy.
    if (tid == 0) {
        unsigned nP = min(sNP, (unsigned)SCAP), nY = min(sNY, (unsigned)SCAP);
        sBP = atomicAdd(&g_ccnt[2 * img], nP);
        sBY = atomicAdd(&g_ccnt[2 * img + 1], nY);
        if (sNP > SCAP) g_flag[2 * img] = 1;
        if (sNY > SCAP) g_flag[2 * img + 1] = 1;
    }
    __syncthreads();
    unsigned nP = min(sNP, (unsigned)SCAP), nY = min(sNY, (unsigned)SCAP);
    float* candP = g_cand[2 * img];
    float* candY = g_cand[2 * img + 1];
    for (unsigned i = tid; i < nP; i += 256) { unsigned o = sBP + i; if (o < CAP) candP[o] = sCP[i]; }
    for (unsigned i = tid; i < nY; i += 256) { unsigned o = sBY + i; if (o < CAP) candY[o] = sCY[i]; }
}
__global__ void __launch_bounds__(256) k_scan(const float* P, const float* Y, const void* M) {
    int m = g_mmode;
    if (m == 0) scan_impl<0>(P, Y, M);
    else if (m == 2) scan_impl<2>(P, Y, M);
    else scan_impl<1>(P, Y, M);
}

__global__ void __launch_bounds__(256) k_select() {
    int t = blockIdx.x, img = t >> 1, tid = threadIdx.x;
    __shared__ double redD[8];
    __shared__ unsigned long long redU[8];
    unsigned cnt = g_cnt[img];
    if (cnt == 0) { if (tid == 0) { g_med[t] = 0.f; g_isc[t] = (float)(1.0 / EPSV); g_flag[t] = 0; } return; }
    if (g_flag[t]) return;  // sample/stage failure -> fallback
    unsigned r = (cnt - 1) >> 1;
    unsigned nb_lo = g_nb[t];
    unsigned ncand = g_ccnt[t];
    long long j = (long long)r - (long long)nb_lo;
    if (ncand > CAP || j < 0 || j >= (long long)ncand) { if (tid == 0) g_flag[t] = 1; return; }
    unsigned mkey = radixSelectG(g_cand[t], (int)ncand, (unsigned)j);
    unsigned nl = 0;
    double sl = 0;
    for (int i = tid; i < (int)ncand; i += 256) {
        float v = g_cand[t][i];
        if (monot(v) < mkey) { nl++; sl += (double)v; }
    }
    double sls = blockReduceD(sl, redD);
    __syncthreads();
    unsigned long long nls = blockReduceU(nl, redU);
    if (tid == 0) {
        double med = (double)inv_monot(mkey);
        double nb = (double)nb_lo + (double)nls;
        double Sb = g_sb[t] + sls;
        double abs_sum = g_stot[t] - 2.0 * Sb + med * (2.0 * nb - (double)cnt);
        if (abs_sum < 0.0) abs_sum = 0.0;
        double sc = abs_sum / (double)cnt + EPSV;
        g_med[t] = (float)med;
        g_isc[t] = (float)(1.0 / sc);
    }
}

// Exact fallback (normally all blocks return immediately).
__global__ void __launch_bounds__(256) k_fallback(const float* P, const float* Y, const void* M) {
    int t = blockIdx.x;
    if (g_flag[t] == 0) return;
    int img = t >> 1, tid = threadIdx.x;
    unsigned cnt = g_cnt[img];
    if (cnt == 0) { if (tid == 0) { g_med[t] = 0.f; g_isc[t] = (float)(1.0 / EPSV); } return; }
    const float* src = (t & 1) ? Y : P;
    int mode = g_mmode;
    int base = img * HWSZ;
    unsigned r = (cnt - 1) >> 1;
    __shared__ unsigned sTot;
    __shared__ double sD;
    unsigned key = 0;
    for (int bit = 31; bit >= 0; bit--) {
        unsigned pivot = key | (1u << bit);
        if (tid == 0) sTot = 0u;
        __syncthreads();
        unsigned c = 0;
        for (int i = tid; i < HWSZ; i += 256) {
            bool m = (mode == 0) ? ((const unsigned char*)M)[base + i] != 0
                   : (mode == 2) ? ((const int*)M)[base + i] != 0
                   : ((const float*)M)[base + i] != 0.f;
            if (m && monot(src[base + i]) < pivot) c++;
        }
        for (int o = 16; o; o >>= 1) c += __shfl_down_sync(0xffffffffu, c, o);
        if ((tid & 31) == 0) atomicAdd(&sTot, c);
        __syncthreads();
        if (sTot <= r) key = pivot;
        __syncthreads();
    }
    if (tid == 0) { sTot = 0u; sD = 0.0; }
    __syncthreads();
    unsigned nb = 0;
    double Sb = 0;
    for (int i = tid; i < HWSZ; i += 256) {
        bool m = (mode == 0) ? ((const unsigned char*)M)[base + i] != 0
               : (mode == 2) ? ((const int*)M)[base + i] != 0
               : ((const float*)M)[base + i] != 0.f;
        if (m) {
            float v = src[base + i];
            if (monot(v) < key) { nb++; Sb += (double)v; }
        }
    }
    for (int o = 16; o; o >>= 1) { nb += __shfl_down_sync(0xffffffffu, nb, o); Sb += __shfl_down_sync(0xffffffffu, Sb, o); }
    if ((tid & 31) == 0) { atomicAdd(&sTot, nb); atomicAdd(&sD, Sb); }
    __syncthreads();
    if (tid == 0) {
        double med = (double)inv_monot(key);
        double abs_sum = g_stot[t] - 2.0 * sD + med * (2.0 * (double)sTot - (double)cnt);
        if (abs_sum < 0.0) abs_sum = 0.0;
        double sc = abs_sum / (double)cnt + EPSV;
        g_med[t] = (float)med;
        g_isc[t] = (float)(1.0 / sc);
    }
}

template <int MODE>
__device__ __forceinline__ void main_impl(const float* P, const float* Y, const void* M) {
    __shared__ float sd[BANDSZ + WD + 2];
    __shared__ unsigned char sm[BANDSZ + WD + 2];
    __shared__ double redD[8];
    __shared__ unsigned long long redU[8];
    int img = blockIdx.y, band = blockIdx.x, tid = threadIdx.x;
    bool last = (band == NBANDS - 1);
    int nelem = last ? BANDSZ : (BANDSZ + WD);   // 7252 or 7770
    float medp = g_med[2 * img], medy = g_med[2 * img + 1];
    float iscp = g_isc[2 * img], iscy = g_isc[2 * img + 1];
    int ebase = img * HWSZ + band * BANDSZ;
    int base4 = ebase >> 2;
    int nv = (nelem & ~3) >> 2;                  // 1813 or 1942
    const float4* P4 = (const float4*)P;
    const float4* Y4 = (const float4*)Y;
    for (int v = tid; v < nv; v += 256) {
        float4 p = P4[base4 + v];
        float4 q = Y4[base4 + v];
        bool m0, m1, m2, m3;
        loadMask4<MODE>(M, base4 + v, m0, m1, m2, m3);
        int o = v * 4;
        sd[o]     = (p.x - medp) * iscp - (q.x - medy) * iscy; sm[o]     = m0;
        sd[o + 1] = (p.y - medp) * iscp - (q.y - medy) * iscy; sm[o + 1] = m1;
        sd[o + 2] = (p.z - medp) * iscp - (q.z - medy) * iscy; sm[o + 2] = m2;
        sd[o + 3] = (p.w - medp) * iscp - (q.w - medy) * iscy; sm[o + 3] = m3;
    }
    if (!last && tid < 2) {   // 7770 = 1942*4 + 2 leftover
        int o = 7768 + tid;
        int gi = ebase + o;
        float p = P[gi], q = Y[gi];
        sd[o] = (p - medp) * iscp - (q - medy) * iscy;
        sm[o] = maskAt<MODE>(M, gi) ? 1 : 0;
    }
    __syncthreads();
    float rho = 0.f, gx = 0.f, gy = 0.f;
    unsigned cx = 0, cy = 0;
    int npair = last ? (13 * WD) : BANDSZ;
    for (int i = tid; i < BANDSZ; i += 256) {
        int c = i - (i / WD) * WD;
        unsigned char m = sm[i];
        float d = sd[i];
        if (m) {
            rho += fabsf(d);
            if (c < WD - 1 && sm[i + 1]) { gx += fabsf(sd[i + 1] - d); cx++; }
            if (i < npair && sm[i + WD]) { gy += fabsf(sd[i + WD] - d); cy++; }
        }
    }
    // 2x2 pool -> level 1 (7 pooled rows x 259)
    float* d1 = d1buf + img * L1SZ + band * 7 * L1W;
    unsigned char* m1 = m1buf + img * L1SZ + band * 7 * L1W;
    for (int i = tid; i < 7 * L1W; i += 256) {
        int pr = i / L1W, pc = i - pr * L1W;
        int o0 = (2 * pr) * WD + 2 * pc;
        d1[i] = 0.25f * (sd[o0] + sd[o0 + 1] + sd[o0 + WD] + sd[o0 + WD + 1]);
        m1[i] = sm[o0] | sm[o0 + 1] | sm[o0 + WD] | sm[o0 + WD + 1];
    }
    double r1 = blockReduceD((double)rho, redD); __syncthreads();
    double r2 = blockReduceD((double)gx, redD);  __syncthreads();
    double r3 = blockReduceD((double)gy, redD);  __syncthreads();
    unsigned long long u1 = blockReduceU(cx, redU); __syncthreads();
    unsigned long long u2 = blockReduceU(cy, redU);
    if (tid == 0) {
        atomicAdd(&g_rho[img], r1);
        atomicAdd(&g_gx[0], r2); atomicAdd(&g_gy[0], r3);
        atomicAdd(&g_cx[0], u1); atomicAdd(&g_cy[0], u2);
    }
}
__global__ void __launch_bounds__(256) k_main(const float* P, const float* Y, const void* M) {
    int m = g_mmode;
    if (m == 0) main_impl<0>(P, Y, M);
    else if (m == 2) main_impl<2>(P, Y, M);
    else main_impl<1>(P, Y, M);
}

__global__ void __launch_bounds__(256) k_grad(int lvl) {
    const float* d; const unsigned char* m; int Hc, Wc;
    if (lvl == 1) { d = d1buf; m = m1buf; Hc = 259; Wc = 259; }
    else if (lvl == 2) { d = d2buf; m = m2buf; Hc = 129; Wc = 129; }
    else { d = d3buf; m = m3buf; Hc = 64; Wc = 64; }
    __shared__ double redD[8];
    __shared__ unsigned long long redU[8];
    int per = Hc * Wc, total = NIMG * per;
    double gx = 0, gy = 0;
    unsigned cx = 0, cy = 0;
    for (int i = blockIdx.x * blockDim.x + threadIdx.x; i < total; i += gridDim.x * blockDim.x) {
        if (!m[i]) continue;
        int rem = i % per;
        int r = rem / Wc, c = rem - r * Wc;
        float dv = d[i];
        if (c < Wc - 1 && m[i + 1]) { gx += (double)fabsf(d[i + 1] - dv); cx++; }
        if (r < Hc - 1 && m[i + Wc]) { gy += (double)fabsf(d[i + Wc] - dv); cy++; }
    }
    double r2 = blockReduceD(gx, redD); __syncthreads();
    double r3 = blockReduceD(gy, redD); __syncthreads();
    unsigned long long u1 = blockReduceU(cx, redU); __syncthreads();
    unsigned long long u2 = blockReduceU(cy, redU);
    if (threadIdx.x == 0) {
        atomicAdd(&g_gx[lvl], r2); atomicAdd(&g_gy[lvl], r3);
        atomicAdd(&g_cx[lvl], u1); atomicAdd(&g_cy[lvl], u2);
    }
}

__global__ void __launch_bounds__(256) k_pool(int lvl) {
    const float* din; const unsigned char* mi; float* dout; unsigned char* mo;
    int Hi, Wi, Ho, Wo;
    if (lvl == 1) { din = d1buf; mi = m1buf; dout = d2buf; mo = m2buf; Hi = 259; Wi = 259; Ho = 129; Wo = 129; }
    else { din = d2buf; mi = m2buf; dout = d3buf; mo = m3buf; Hi = 129; Wi = 129; Ho = 64; Wo = 64; }
    int per = Ho * Wo, total = NIMG * per;
    for (int i = blockIdx.x * blockDim.x + threadIdx.x; i < total; i += gridDim.x * blockDim.x) {
        int img = i / per, rem = i - img * per;
        int r = rem / Wo, c = rem - r * Wo;
        int bi = img * Hi * Wi + (2 * r) * Wi + 2 * c;
        dout[i] = 0.25f * (din[bi] + din[bi + 1] + din[bi + Wi] + din[bi + Wi + 1]);
        mo[i] = mi[bi] | mi[bi + 1] | mi[bi + Wi] | mi[bi + Wi + 1];
    }
}

__global__ void k_final(float* out) {
    if (threadIdx.x == 0 && blockIdx.x == 0) {
        double ssi = 0;
        for (int i = 0; i < NIMG; i++) {
            double v = (double)g_cnt[i];
            if (v < 1.0) v = 1.0;
            ssi += g_rho[i] / v;
        }
        ssi /= (double)NIMG;
        double g = 0;
        for (int s = 0; s < 4; s++) {
            double cx = (double)g_cx[s]; if (cx < 1.0) cx = 1.0;
            double cy = (double)g_cy[s]; if (cy < 1.0) cy = 1.0;
            g += g_gx[s] / cx + g_gy[s] / cy;
        }
        out[0] = (float)(ssi + 0.5 * (g / 4.0));
    }
}

extern "C" void kernel_launch(void* const* d_in, const int* in_sizes, int n_in,
                              void* d_out, int out_size) {
    const float* pred = (const float*)d_in[0];
    const float* yv = (const float*)d_in[1];
    const void* mask = d_in[2];
    float* out = (float*)d_out;

    k_init<<<1, 256>>>(mask);
    k_sample<<<dim3(8, NIMG), 256>>>(pred, yv, mask);
    k_smed<<<128, 256>>>();
    k_scan<<<dim3(32, NIMG), 256>>>(pred, yv, mask);
    k_select<<<128, 256>>>();
    k_fallback<<<128, 256>>>(pred, yv, mask);
    k_main<<<dim3(NBANDS, NIMG), 256>>>(pred, yv, mask);
    k_grad<<<2048, 256>>>(1);
    k_pool<<<1024, 256>>>(1);
    k_grad<<<1024, 256>>>(2);
    k_pool<<<512, 256>>>(2);
    k_grad<<<512, 256>>>(3);
    k_final<<<1, 32>>>(out);
}

// round 5
// speedup vs baseline: 2.1718x; 1.4978x over previous
#include <cuda_runtime.h>
#include <cstdint>

#define HWSZ 268324
#define HW4  67081
#define WD 518
#define NIMG 64
#define CAP 32768
#define SCAP 1024
#define EPSV 1e-8
#define SAMPN 12032
#define SCHUNKS 47
#define SSTRIDE 5708
#define BANDSZ 7252        // 14 rows * 518
#define NBANDS 37
#define L1W 259
#define L1SZ (259*259)
#define G8 33540           // full 8-element groups per image

// ---------------- static device scratch ----------------
__device__ int g_mmode;
__device__ unsigned g_scnt[NIMG];
__device__ float g_sampP[NIMG][SAMPN];
__device__ float g_sampY[NIMG][SAMPN];
__device__ float g_vlo[128], g_vhi[128];
__device__ int g_flag[128];
__device__ unsigned g_cnt[NIMG];
__device__ unsigned g_nb[128];
__device__ double g_sb[128];
__device__ double g_stot[128];
__device__ unsigned g_ccnt[128];
__device__ float g_cand[128][CAP];
__device__ float g_med[128], g_isc[128];
__device__ double g_rho[NIMG];
__device__ double g_gx[4], g_gy[4];
__device__ unsigned long long g_cx[4], g_cy[4];

__device__ float d1buf[NIMG * L1SZ];
__device__ unsigned char m1buf[NIMG * L1SZ];
__device__ float d2buf[NIMG * 129 * 129];
__device__ unsigned char m2buf[NIMG * 129 * 129];
__device__ float d3buf[NIMG * 64 * 64];
__device__ unsigned char m3buf[NIMG * 64 * 64];

// ---------------- helpers ----------------
__device__ __forceinline__ unsigned monot(float x) {
    unsigned u = __float_as_uint(x);
    return (u >> 31) ? ~u : (u | 0x80000000u);
}
__device__ __forceinline__ float inv_monot(unsigned k) {
    unsigned u = (k >> 31) ? (k & 0x7FFFFFFFu) : ~k;
    return __uint_as_float(u);
}

template <int MODE>
__device__ __forceinline__ bool maskAt(const void* m, int i) {
    if (MODE == 0) return ((const unsigned char*)m)[i] != 0;
    if (MODE == 2) return ((const int*)m)[i] != 0;
    return ((const float*)m)[i] != 0.f;
}
template <int MODE>
__device__ __forceinline__ void loadMask4(const void* m, int g4, bool& b0, bool& b1, bool& b2, bool& b3) {
    if (MODE == 0) { uchar4 v = ((const uchar4*)m)[g4]; b0 = v.x; b1 = v.y; b2 = v.z; b3 = v.w; }
    else if (MODE == 2) { int4 v = ((const int4*)m)[g4]; b0 = v.x != 0; b1 = v.y != 0; b2 = v.z != 0; b3 = v.w != 0; }
    else { float4 v = ((const float4*)m)[g4]; b0 = v.x != 0.f; b1 = v.y != 0.f; b2 = v.z != 0.f; b3 = v.w != 0.f; }
}

__device__ __forceinline__ double blockReduceD(double v, double* sh) {
    for (int o = 16; o; o >>= 1) v += __shfl_down_sync(0xffffffffu, v, o);
    int w = threadIdx.x >> 5, l = threadIdx.x & 31;
    if (l == 0) sh[w] = v;
    __syncthreads();
    double r = 0;
    if (threadIdx.x < 8) {
        r = sh[threadIdx.x];
        for (int o = 4; o; o >>= 1) r += __shfl_down_sync(0xffu, r, o);
    }
    return r;
}
__device__ __forceinline__ unsigned long long blockReduceU(unsigned long long v, unsigned long long* sh) {
    for (int o = 16; o; o >>= 1) v += __shfl_down_sync(0xffffffffu, v, o);
    int w = threadIdx.x >> 5, l = threadIdx.x & 31;
    if (l == 0) sh[w] = v;
    __syncthreads();
    unsigned long long r = 0;
    if (threadIdx.x < 8) {
        r = sh[threadIdx.x];
        for (int o = 4; o; o >>= 1) r += __shfl_down_sync(0xffu, r, o);
    }
    return r;
}

__device__ __forceinline__ void warpPushS(bool d, float v, unsigned* ctr, float* arr) {
    unsigned b = __ballot_sync(0xffffffffu, d);
    if (!b) return;
    int lane = threadIdx.x & 31;
    unsigned pos = 0;
    int leader = __ffs(b) - 1;
    if (lane == leader) pos = atomicAdd(ctr, (unsigned)__popc(b));
    pos = __shfl_sync(0xffffffffu, pos, leader);
    if (d) {
        unsigned o = pos + __popc(b & ((1u << lane) - 1));
        if (o < SCAP) arr[o] = v;
    }
}

// 4-bit radix select over smem monot keys. Block-collective (256 threads).
__device__ unsigned radixSelectKeysSm(const unsigned* keys, int n, unsigned rank) {
    __shared__ unsigned cnts[8][16];
    __shared__ unsigned sPrefix, sRank;
    int tid = threadIdx.x, w = tid >> 5;
    if (tid == 0) { sPrefix = 0u; sRank = rank; }
    for (int shift = 28; shift >= 0; shift -= 4) {
        if (tid < 128) ((unsigned*)cnts)[tid] = 0u;
        __syncthreads();
        unsigned prefix = sPrefix;
        unsigned hiMask = (shift == 28) ? 0u : (0xFFFFFFFFu << (shift + 4));
        for (int i = tid; i < n; i += 256) {
            unsigned k = keys[i];
            if ((k & hiMask) == prefix) atomicAdd(&cnts[w][(k >> shift) & 15], 1u);
        }
        __syncthreads();
        if (tid == 0) {
            unsigned r = sRank, cum = 0;
            for (int d = 0; d < 16; d++) {
                unsigned c = 0;
                for (int ww = 0; ww < 8; ww++) c += cnts[ww][d];
                if (cum + c > r) { sPrefix = prefix | ((unsigned)d << shift); sRank = r - cum; break; }
                cum += c;
            }
        }
        __syncthreads();
    }
    return sPrefix;
}

// same over global float array
__device__ unsigned radixSelectG(const float* vals, int n, unsigned rank) {
    __shared__ unsigned cnts[8][16];
    __shared__ unsigned sPrefix, sRank;
    int tid = threadIdx.x, w = tid >> 5;
    if (tid == 0) { sPrefix = 0u; sRank = rank; }
    for (int shift = 28; shift >= 0; shift -= 4) {
        if (tid < 128) ((unsigned*)cnts)[tid] = 0u;
        __syncthreads();
        unsigned prefix = sPrefix;
        unsigned hiMask = (shift == 28) ? 0u : (0xFFFFFFFFu << (shift + 4));
        for (int i = tid; i < n; i += 256) {
            unsigned k = monot(vals[i]);
            if ((k & hiMask) == prefix) atomicAdd(&cnts[w][(k >> shift) & 15], 1u);
        }
        __syncthreads();
        if (tid == 0) {
            unsigned r = sRank, cum = 0;
            for (int d = 0; d < 16; d++) {
                unsigned c = 0;
                for (int ww = 0; ww < 8; ww++) c += cnts[ww][d];
                if (cum + c > r) { sPrefix = prefix | ((unsigned)d << shift); sRank = r - cum; break; }
                cum += c;
            }
        }
        __syncthreads();
    }
    return sPrefix;
}

// ---------------- kernels ----------------
__global__ void k_init(const void* mask) {
    int tid = threadIdx.x;
    for (int i = tid; i < NIMG; i += 256) { g_scnt[i] = 0u; g_cnt[i] = 0u; g_rho[i] = 0.0; }
    for (int i = tid; i < 128; i += 256) {
        g_nb[i] = 0u; g_sb[i] = 0.0; g_stot[i] = 0.0; g_ccnt[i] = 0u; g_flag[i] = 0;
    }
    if (tid < 4) { g_gx[tid] = 0.0; g_gy[tid] = 0.0; g_cx[tid] = 0ull; g_cy[tid] = 0ull; }
    if (tid == 0) {
        const unsigned char* b = (const unsigned char*)mask;
        bool nonbin = false, offnz = false;
        for (int j = 0; j < 256; j++) {
            unsigned char v = b[j];
            if (v > 1) nonbin = true;
            if ((j & 3) && v) offnz = true;
        }
        g_mmode = nonbin ? 1 : (offnz ? 0 : 2);
    }
}

template <int MODE>
__device__ __forceinline__ void sample_impl(const float* P, const float* Y, const void* M) {
    int img = blockIdx.y, tid = threadIdx.x;
    for (int ch = blockIdx.x * 8; ch < blockIdx.x * 8 + 8; ch++) {
        if (ch >= SCHUNKS) break;
        int idx = img * HWSZ + ch * SSTRIDE + tid;
        bool v = maskAt<MODE>(M, idx);
        float p = P[idx], q = Y[idx];
        unsigned b = __ballot_sync(0xffffffffu, v);
        if (b) {
            int lane = tid & 31;
            unsigned pos = 0;
            int leader = __ffs(b) - 1;
            if (lane == leader) pos = atomicAdd(&g_scnt[img], (unsigned)__popc(b));
            pos = __shfl_sync(0xffffffffu, pos, leader);
            if (v) {
                unsigned o = pos + __popc(b & ((1u << lane) - 1));
                if (o < SAMPN) { g_sampP[img][o] = p; g_sampY[img][o] = q; }
            }
        }
    }
}
__global__ void __launch_bounds__(256) k_sample(const float* P, const float* Y, const void* M) {
    int m = g_mmode;
    if (m == 0) sample_impl<0>(P, Y, M);
    else if (m == 2) sample_impl<2>(P, Y, M);
    else sample_impl<1>(P, Y, M);
}

__global__ void __launch_bounds__(256) k_smed() {
    __shared__ unsigned skeys[SAMPN];
    int t = blockIdx.x, img = t >> 1, tid = threadIdx.x;
    int n = (int)min(g_scnt[img], (unsigned)SAMPN);
    if (n == 0) {
        if (tid == 0) { g_vlo[t] = __int_as_float(0x7f800000); g_vhi[t] = __int_as_float(0xff800000); }
        return;
    }
    const float* src = (t & 1) ? g_sampY[img] : g_sampP[img];
    for (int i = tid; i < n; i += 256) skeys[i] = monot(src[i]);
    __syncthreads();
    unsigned rlo = (unsigned)(((long long)(n - 1) * 475) / 1000);
    unsigned rhi = (unsigned)((((long long)(n - 1) * 525) + 999) / 1000);
    if (rhi > (unsigned)(n - 1)) rhi = (unsigned)(n - 1);
    unsigned klo = radixSelectKeysSm(skeys, n, rlo);
    unsigned khi = radixSelectKeysSm(skeys, n, rhi);
    if (tid == 0) { g_vlo[t] = inv_monot(klo); g_vhi[t] = inv_monot(khi); }
}

template <int MODE>
__device__ __forceinline__ void scan_impl(const float* P, const float* Y, const void* M) {
    __shared__ float sCP[SCAP], sCY[SCAP];
    __shared__ unsigned sNP, sNY, sBP, sBY;
    __shared__ double redD[8];
    __shared__ unsigned long long redU[8];
    int img = blockIdx.y, bx = blockIdx.x, tid = threadIdx.x;
    if (tid == 0) { sNP = 0u; sNY = 0u; }
    __syncthreads();
    int s = (bx * G8) >> 5;
    int e = ((bx + 1) * G8) >> 5;
    int ng = e - s;
    int iters = (ng + 255) >> 8;       // uniform trip count across the block
    float vloP = g_vlo[2 * img], vhiP = g_vhi[2 * img];
    float vloY = g_vlo[2 * img + 1], vhiY = g_vhi[2 * img + 1];
    const float4* P4 = (const float4*)P;
    const float4* Y4 = (const float4*)Y;
    unsigned cnt = 0, nbP = 0, nbY = 0;
    float sbP = 0.f, sbY = 0.f, stP = 0.f, stY = 0.f;
    for (int it = 0; it < iters; it++) {
        int g = s + it * 256 + tid;
        bool ok = g < e;
        int idx4 = img * HW4 + 2 * (ok ? g : s);
        float4 p0 = P4[idx4], p1 = P4[idx4 + 1];
        float4 q0 = Y4[idx4], q1 = Y4[idx4 + 1];
        float pv[8] = {p0.x, p0.y, p0.z, p0.w, p1.x, p1.y, p1.z, p1.w};
        float qv[8] = {q0.x, q0.y, q0.z, q0.w, q1.x, q1.y, q1.z, q1.w};
        bool mv[8];
        if (MODE == 0) {
            const unsigned* Mu = (const unsigned*)M;
            unsigned ma = Mu[idx4], mb = Mu[idx4 + 1];
#pragma unroll
            for (int j = 0; j < 4; j++) { mv[j] = (ma >> (8 * j)) & 0xffu; mv[4 + j] = (mb >> (8 * j)) & 0xffu; }
        } else {
            loadMask4<MODE>(M, idx4, mv[0], mv[1], mv[2], mv[3]);
            loadMask4<MODE>(M, idx4 + 1, mv[4], mv[5], mv[6], mv[7]);
        }
#pragma unroll
        for (int j = 0; j < 8; j++) {
            bool m = ok && mv[j];
            bool pushP = false, pushY = false;
            if (m) {
                cnt++;
                float a = pv[j];
                stP += a;
                if (a < vloP) { nbP++; sbP += a; }
                else if (a <= vhiP) pushP = true;
                float b = qv[j];
                stY += b;
                if (b < vloY) { nbY++; sbY += b; }
                else if (b <= vhiY) pushY = true;
            }
            warpPushS(pushP, pv[j], &sNP, sCP);
            warpPushS(pushY, qv[j], &sNY, sCY);
        }
    }
    // tail: 4 leftover elements per image, handled by warp 0 of block 31
    if (bx == 31 && tid < 32) {
        int ei = img * HWSZ + G8 * 8 + tid;
        bool valid = tid < 4;
        bool m = valid && maskAt<MODE>(M, ei);
        float a = m ? P[ei] : 0.f;
        float b = m ? Y[ei] : 0.f;
        bool pushP = false, pushY = false;
        if (m) {
            cnt++;
            stP += a;
            if (a < vloP) { nbP++; sbP += a; }
            else if (a <= vhiP) pushP = true;
            stY += b;
            if (b < vloY) { nbY++; sbY += b; }
            else if (b <= vhiY) pushY = true;
        }
        warpPushS(pushP, a, &sNP, sCP);
        warpPushS(pushY, b, &sNY, sCY);
    }
    double r;
    r = blockReduceD((double)sbP, redD); if (tid == 0) atomicAdd(&g_sb[2 * img], r); __syncthreads();
    r = blockReduceD((double)sbY, redD); if (tid == 0) atomicAdd(&g_sb[2 * img + 1], r); __syncthreads();
    r = blockReduceD((double)stP, redD); if (tid == 0) atomicAdd(&g_stot[2 * img], r); __syncthreads();
    r = blockReduceD((double)stY, redD); if (tid == 0) atomicAdd(&g_stot[2 * img + 1], r); __syncthreads();
    unsigned long long u;
    u = blockReduceU(cnt, redU); if (tid == 0) atomicAdd(&g_cnt[img], (unsigned)u); __syncthreads();
    u = blockReduceU(nbP, redU); if (tid == 0) atomicAdd(&g_nb[2 * img], (unsigned)u); __syncthreads();
    u = blockReduceU(nbY, redU); if (tid == 0) atomicAdd(&g_nb[2 * img + 1], (unsigned)u);
    __syncthreads();
    if (tid == 0) {
        unsigned nP = min(sNP, (unsigned)SCAP), nY = min(sNY, (unsigned)SCAP);
        sBP = atomicAdd(&g_ccnt[2 * img], nP);
        sBY = atomicAdd(&g_ccnt[2 * img + 1], nY);
        if (sNP > SCAP) g_flag[2 * img] = 1;
        if (sNY > SCAP) g_flag[2 * img + 1] = 1;
    }
    __syncthreads();
    unsigned nP = min(sNP, (unsigned)SCAP), nY = min(sNY, (unsigned)SCAP);
    float* candP = g_cand[2 * img];
    float* candY = g_cand[2 * img + 1];
    for (unsigned i = tid; i < nP; i += 256) { unsigned o = sBP + i; if (o < CAP) candP[o] = sCP[i]; }
    for (unsigned i = tid; i < nY; i += 256) { unsigned o = sBY + i; if (o < CAP) candY[o] = sCY[i]; }
}
__global__ void __launch_bounds__(256) k_scan(const float* P, const float* Y, const void* M) {
    int m = g_mmode;
    if (m == 0) scan_impl<0>(P, Y, M);
    else if (m == 2) scan_impl<2>(P, Y, M);
    else scan_impl<1>(P, Y, M);
}

__global__ void __launch_bounds__(256) k_select() {
    int t = blockIdx.x, img = t >> 1, tid = threadIdx.x;
    __shared__ double redD[8];
    __shared__ unsigned long long redU[8];
    unsigned cnt = g_cnt[img];
    if (cnt == 0) { if (tid == 0) { g_med[t] = 0.f; g_isc[t] = (float)(1.0 / EPSV); g_flag[t] = 0; } return; }
    if (g_flag[t]) return;
    unsigned r = (cnt - 1) >> 1;
    unsigned nb_lo = g_nb[t];
    unsigned ncand = g_ccnt[t];
    long long j = (long long)r - (long long)nb_lo;
    if (ncand > CAP || j < 0 || j >= (long long)ncand) { if (tid == 0) g_flag[t] = 1; return; }
    unsigned mkey = radixSelectG(g_cand[t], (int)ncand, (unsigned)j);
    unsigned nl = 0;
    double sl = 0;
    for (int i = tid; i < (int)ncand; i += 256) {
        float v = g_cand[t][i];
        if (monot(v) < mkey) { nl++; sl += (double)v; }
    }
    double sls = blockReduceD(sl, redD);
    __syncthreads();
    unsigned long long nls = blockReduceU(nl, redU);
    if (tid == 0) {
        double med = (double)inv_monot(mkey);
        double nb = (double)nb_lo + (double)nls;
        double Sb = g_sb[t] + sls;
        double abs_sum = g_stot[t] - 2.0 * Sb + med * (2.0 * nb - (double)cnt);
        if (abs_sum < 0.0) abs_sum = 0.0;
        double sc = abs_sum / (double)cnt + EPSV;
        g_med[t] = (float)med;
        g_isc[t] = (float)(1.0 / sc);
    }
}

// Exact fallback (normally every block returns immediately).
__global__ void __launch_bounds__(256) k_fallback(const float* P, const float* Y, const void* M) {
    int t = blockIdx.x;
    if (g_flag[t] == 0) return;
    int img = t >> 1, tid = threadIdx.x;
    unsigned cnt = g_cnt[img];
    if (cnt == 0) { if (tid == 0) { g_med[t] = 0.f; g_isc[t] = (float)(1.0 / EPSV); } return; }
    const float* src = (t & 1) ? Y : P;
    int mode = g_mmode;
    int base = img * HWSZ;
    unsigned r = (cnt - 1) >> 1;
    __shared__ unsigned sTot;
    __shared__ double sD;
    unsigned key = 0;
    for (int bit = 31; bit >= 0; bit--) {
        unsigned pivot = key | (1u << bit);
        if (tid == 0) sTot = 0u;
        __syncthreads();
        unsigned c = 0;
        for (int i = tid; i < HWSZ; i += 256) {
            bool m = (mode == 0) ? ((const unsigned char*)M)[base + i] != 0
                   : (mode == 2) ? ((const int*)M)[base + i] != 0
                   : ((const float*)M)[base + i] != 0.f;
            if (m && monot(src[base + i]) < pivot) c++;
        }
        for (int o = 16; o; o >>= 1) c += __shfl_down_sync(0xffffffffu, c, o);
        if ((tid & 31) == 0) atomicAdd(&sTot, c);
        __syncthreads();
        if (sTot <= r) key = pivot;
        __syncthreads();
    }
    if (tid == 0) { sTot = 0u; sD = 0.0; }
    __syncthreads();
    unsigned nb = 0;
    double Sb = 0;
    for (int i = tid; i < HWSZ; i += 256) {
        bool m = (mode == 0) ? ((const unsigned char*)M)[base + i] != 0
               : (mode == 2) ? ((const int*)M)[base + i] != 0
               : ((const float*)M)[base + i] != 0.f;
        if (m) {
            float v = src[base + i];
            if (monot(v) < key) { nb++; Sb += (double)v; }
        }
    }
    for (int o = 16; o; o >>= 1) { nb += __shfl_down_sync(0xffffffffu, nb, o); Sb += __shfl_down_sync(0xffffffffu, Sb, o); }
    if ((tid & 31) == 0) { atomicAdd(&sTot, nb); atomicAdd(&sD, Sb); }
    __syncthreads();
    if (tid == 0) {
        double med = (double)inv_monot(key);
        double abs_sum = g_stot[t] - 2.0 * sD + med * (2.0 * (double)sTot - (double)cnt);
        if (abs_sum < 0.0) abs_sum = 0.0;
        double sc = abs_sum / (double)cnt + EPSV;
        g_med[t] = (float)med;
        g_isc[t] = (float)(1.0 / sc);
    }
}

template <int MODE>
__device__ __forceinline__ void main_impl(const float* P, const float* Y, const void* M) {
    __shared__ float sd[BANDSZ + WD + 4];
    __shared__ unsigned char sm[BANDSZ + WD + 4];
    __shared__ double redD[8];
    __shared__ unsigned long long redU[8];
    int img = blockIdx.y, band = blockIdx.x, tid = threadIdx.x;
    bool last = (band == NBANDS - 1);
    int nelem = last ? BANDSZ : (BANDSZ + WD);
    float medp = g_med[2 * img], medy = g_med[2 * img + 1];
    float iscp = g_isc[2 * img], iscy = g_isc[2 * img + 1];
    int ebase = img * HWSZ + band * BANDSZ;
    int base4 = ebase >> 2;
    int nv = (nelem & ~3) >> 2;
    const float4* P4 = (const float4*)P;
    const float4* Y4 = (const float4*)Y;
    for (int v = tid; v < nv; v += 256) {
        float4 p = P4[base4 + v];
        float4 q = Y4[base4 + v];
        bool m0, m1, m2, m3;
        loadMask4<MODE>(M, base4 + v, m0, m1, m2, m3);
        int o = v * 4;
        sd[o]     = (p.x - medp) * iscp - (q.x - medy) * iscy; sm[o]     = m0;
        sd[o + 1] = (p.y - medp) * iscp - (q.y - medy) * iscy; sm[o + 1] = m1;
        sd[o + 2] = (p.z - medp) * iscp - (q.z - medy) * iscy; sm[o + 2] = m2;
        sd[o + 3] = (p.w - medp) * iscp - (q.w - medy) * iscy; sm[o + 3] = m3;
    }
    if (!last && tid < 2) {   // 7770 = 1942*4 + 2 leftover
        int o = 7768 + tid;
        int gi = ebase + o;
        float p = P[gi], q = Y[gi];
        sd[o] = (p - medp) * iscp - (q - medy) * iscy;
        sm[o] = maskAt<MODE>(M, gi) ? 1 : 0;
    }
    __syncthreads();
    float rho = 0.f, gx = 0.f, gy = 0.f;
    unsigned cx = 0, cy = 0;
    int nprow = last ? 13 : 14;
    {
        int i = tid, row = 0, c = tid;   // tid < 256 < WD
        while (i < BANDSZ) {
            unsigned char m = sm[i];
            float d = sd[i];
            if (m) {
                rho += fabsf(d);
                if (c < WD - 1 && sm[i + 1]) { gx += fabsf(sd[i + 1] - d); cx++; }
                if (row < nprow && sm[i + WD]) { gy += fabsf(sd[i + WD] - d); cy++; }
            }
            i += 256; c += 256;
            if (c >= WD) { c -= WD; row++; }
        }
    }
    // 2x2 pool -> level 1 (7 pooled rows x 259)
    float* d1 = d1buf + img * L1SZ + band * 7 * L1W;
    unsigned char* m1 = m1buf + img * L1SZ + band * 7 * L1W;
    {
        int pi = tid, pr = 0, pc = tid;  // tid < 256 < L1W
        while (pi < 7 * L1W) {
            int o0 = (2 * pr) * WD + 2 * pc;
            d1[pi] = 0.25f * (sd[o0] + sd[o0 + 1] + sd[o0 + WD] + sd[o0 + WD + 1]);
            m1[pi] = sm[o0] | sm[o0 + 1] | sm[o0 + WD] | sm[o0 + WD + 1];
            pi += 256; pc += 256;
            if (pc >= L1W) { pc -= L1W; pr++; }
        }
    }
    double r1 = blockReduceD((double)rho, redD); __syncthreads();
    double r2 = blockReduceD((double)gx, redD);  __syncthreads();
    double r3 = blockReduceD((double)gy, redD);  __syncthreads();
    unsigned long long u1 = blockReduceU(cx, redU); __syncthreads();
    unsigned long long u2 = blockReduceU(cy, redU);
    if (tid == 0) {
        atomicAdd(&g_rho[img], r1);
        atomicAdd(&g_gx[0], r2); atomicAdd(&g_gy[0], r3);
        atomicAdd(&g_cx[0], u1); atomicAdd(&g_cy[0], u2);
    }
}
__global__ void __launch_bounds__(256) k_main(const float* P, const float* Y, const void* M) {
    int m = g_mmode;
    if (m == 0) main_impl<0>(P, Y, M);
    else if (m == 2) main_impl<2>(P, Y, M);
    else main_impl<1>(P, Y, M);
}

template <int LVL, int HC, int WC>
__global__ void __launch_bounds__(256) k_grad() {
    const float* d;
    const unsigned char* m;
    if (LVL == 1) { d = d1buf; m = m1buf; }
    else if (LVL == 2) { d = d2buf; m = m2buf; }
    else { d = d3buf; m = m3buf; }
    __shared__ double redD[8];
    __shared__ unsigned long long redU[8];
    constexpr int per = HC * WC;
    constexpr int total = NIMG * per;
    float gx = 0.f, gy = 0.f;
    unsigned cx = 0, cy = 0;
    for (int i = blockIdx.x * blockDim.x + threadIdx.x; i < total; i += gridDim.x * blockDim.x) {
        if (!m[i]) continue;
        int rem = i % per;
        int r = rem / WC, c = rem - r * WC;
        float dv = d[i];
        if (c < WC - 1 && m[i + 1]) { gx += fabsf(d[i + 1] - dv); cx++; }
        if (r < HC - 1 && m[i + WC]) { gy += fabsf(d[i + WC] - dv); cy++; }
    }
    double r2 = blockReduceD((double)gx, redD); __syncthreads();
    double r3 = blockReduceD((double)gy, redD); __syncthreads();
    unsigned long long u1 = blockReduceU(cx, redU); __syncthreads();
    unsigned long long u2 = blockReduceU(cy, redU);
    if (threadIdx.x == 0) {
        atomicAdd(&g_gx[LVL], r2); atomicAdd(&g_gy[LVL], r3);
        atomicAdd(&g_cx[LVL], u1); atomicAdd(&g_cy[LVL], u2);
    }
}

template <int LVL, int HI, int WI, int HO, int WO>
__global__ void __launch_bounds__(256) k_pool() {
    const float* din; const unsigned char* mi; float* dout; unsigned char* mo;
    if (LVL == 1) { din = d1buf; mi = m1buf; dout = d2buf; mo = m2buf; }
    else { din = d2buf; mi = m2buf; dout = d3buf; mo = m3buf; }
    constexpr int per = HO * WO;
    constexpr int total = NIMG * per;
    for (int i = blockIdx.x * blockDim.x + threadIdx.x; i < total; i += gridDim.x * blockDim.x) {
        int img = i / per, rem = i - img * per;
        int r = rem / WO, c = rem - r * WO;
        int bi = img * HI * WI + (2 * r) * WI + 2 * c;
        dout[i] = 0.25f * (din[bi] + din[bi + 1] + din[bi + WI] + din[bi + WI + 1]);
        mo[i] = mi[bi] | mi[bi + 1] | mi[bi + WI] | mi[bi + WI + 1];
    }
}

__global__ void k_final(float* out) {
    if (threadIdx.x == 0 && blockIdx.x == 0) {
        double ssi = 0;
        for (int i = 0; i < NIMG; i++) {
            double v = (double)g_cnt[i];
            if (v < 1.0) v = 1.0;
            ssi += g_rho[i] / v;
        }
        ssi /= (double)NIMG;
        double g = 0;
        for (int s = 0; s < 4; s++) {
            double cx = (double)g_cx[s]; if (cx < 1.0) cx = 1.0;
            double cy = (double)g_cy[s]; if (cy < 1.0) cy = 1.0;
            g += g_gx[s] / cx + g_gy[s] / cy;
        }
        out[0] = (float)(ssi + 0.5 * (g / 4.0));
    }
}

extern "C" void kernel_launch(void* const* d_in, const int* in_sizes, int n_in,
                              void* d_out, int out_size) {
    const float* pred = (const float*)d_in[0];
    const float* yv = (const float*)d_in[1];
    const void* mask = d_in[2];
    float* out = (float*)d_out;

    k_init<<<1, 256>>>(mask);
    k_sample<<<dim3(6, NIMG), 256>>>(pred, yv, mask);
    k_smed<<<128, 256>>>();
    k_scan<<<dim3(32, NIMG), 256>>>(pred, yv, mask);
    k_select<<<128, 256>>>();
    k_fallback<<<128, 256>>>(pred, yv, mask);
    k_main<<<dim3(NBANDS, NIMG), 256>>>(pred, yv, mask);
    k_grad<1, 259, 259><<<2048, 256>>>();
    k_pool<1, 259, 259, 129, 129><<<1024, 256>>>();
    k_grad<2, 129, 129><<<512, 256>>>();
    k_pool<2, 129, 129, 64, 64><<<256, 256>>>();
    k_grad<3, 64, 64><<<256, 256>>>();
    k_final<<<1, 32>>>(out);
}

// round 6
// speedup vs baseline: 2.4503x; 1.1282x over previous
#include <cuda_runtime.h>
#include <cstdint>

#define HWSZ 268324
#define HW4  67081
#define WD 518
#define NIMG 64
#define CAP 32768
#define SLOTS 12
#define EPSV 1e-8
#define SAMPN 8192
#define SCHUNKS 32
#define SSTRIDE 8385
#define BANDSZ 7252        // 14 rows * 518
#define NBANDS 37
#define L1W 259
#define L1SZ (259*259)
#define G8 33540           // full 8-element groups per image

// ---------------- static device scratch ----------------
__device__ int g_mmode;
__device__ float g_vlo[128], g_vhi[128];
__device__ int g_flag[128];
__device__ unsigned g_cnt[NIMG];
__device__ unsigned g_nb[128];
__device__ double g_sb[128];
__device__ double g_stot[128];
__device__ unsigned g_ccnt[128];
__device__ float g_cand[128][CAP];
__device__ float g_med[128], g_isc[128];
__device__ double g_rho[NIMG];
__device__ double g_gx[4], g_gy[4];
__device__ unsigned long long g_cx[4], g_cy[4];

__device__ float d1buf[NIMG * L1SZ];
__device__ unsigned char m1buf[NIMG * L1SZ];
__device__ float d2buf[NIMG * 129 * 129];
__device__ unsigned char m2buf[NIMG * 129 * 129];
__device__ float d3buf[NIMG * 64 * 64];
__device__ unsigned char m3buf[NIMG * 64 * 64];

// ---------------- helpers ----------------
__device__ __forceinline__ unsigned monot(float x) {
    unsigned u = __float_as_uint(x);
    return (u >> 31) ? ~u : (u | 0x80000000u);
}
__device__ __forceinline__ float inv_monot(unsigned k) {
    unsigned u = (k >> 31) ? (k & 0x7FFFFFFFu) : ~k;
    return __uint_as_float(u);
}
__device__ __forceinline__ bool maskRT(const void* m, int i, int mode) {
    return (mode == 0) ? ((const unsigned char*)m)[i] != 0
         : (mode == 2) ? ((const int*)m)[i] != 0
         : ((const float*)m)[i] != 0.f;
}

template <int MODE>
__device__ __forceinline__ bool maskAt(const void* m, int i) {
    if (MODE == 0) return ((const unsigned char*)m)[i] != 0;
    if (MODE == 2) return ((const int*)m)[i] != 0;
    return ((const float*)m)[i] != 0.f;
}
template <int MODE>
__device__ __forceinline__ void loadMask4(const void* m, int g4, bool& b0, bool& b1, bool& b2, bool& b3) {
    if (MODE == 0) { uchar4 v = ((const uchar4*)m)[g4]; b0 = v.x; b1 = v.y; b2 = v.z; b3 = v.w; }
    else if (MODE == 2) { int4 v = ((const int4*)m)[g4]; b0 = v.x != 0; b1 = v.y != 0; b2 = v.z != 0; b3 = v.w != 0; }
    else { float4 v = ((const float4*)m)[g4]; b0 = v.x != 0.f; b1 = v.y != 0.f; b2 = v.z != 0.f; b3 = v.w != 0.f; }
}

template <int NT>
__device__ __forceinline__ double blockReduceD(double v, double* sh) {
    constexpr int NW = NT / 32;
    for (int o = 16; o; o >>= 1) v += __shfl_down_sync(0xffffffffu, v, o);
    int w = threadIdx.x >> 5, l = threadIdx.x & 31;
    if (l == 0) sh[w] = v;
    __syncthreads();
    double r = 0;
    if (threadIdx.x < NW) {
        r = sh[threadIdx.x];
        for (int o = NW / 2; o; o >>= 1) r += __shfl_down_sync((unsigned)((1ull << NW) - 1), r, o);
    }
    return r;
}
template <int NT>
__device__ __forceinline__ unsigned long long blockReduceU(unsigned long long v, unsigned long long* sh) {
    constexpr int NW = NT / 32;
    for (int o = 16; o; o >>= 1) v += __shfl_down_sync(0xffffffffu, v, o);
    int w = threadIdx.x >> 5, l = threadIdx.x & 31;
    if (l == 0) sh[w] = v;
    __syncthreads();
    unsigned long long r = 0;
    if (threadIdx.x < NW) {
        r = sh[threadIdx.x];
        for (int o = NW / 2; o; o >>= 1) r += __shfl_down_sync((unsigned)((1ull << NW) - 1), r, o);
    }
    return r;
}

// 4-bit radix select over smem monot keys. Block-collective (256 threads).
__device__ unsigned radixSelectKeysSm(const unsigned* keys, int n, unsigned rank) {
    __shared__ unsigned cnts[8][16];
    __shared__ unsigned sPrefix, sRank;
    int tid = threadIdx.x, w = tid >> 5;
    if (tid == 0) { sPrefix = 0u; sRank = rank; }
    for (int shift = 28; shift >= 0; shift -= 4) {
        if (tid < 128) ((unsigned*)cnts)[tid] = 0u;
        __syncthreads();
        unsigned prefix = sPrefix;
        unsigned hiMask = (shift == 28) ? 0u : (0xFFFFFFFFu << (shift + 4));
        for (int i = tid; i < n; i += 256) {
            unsigned k = keys[i];
            if ((k & hiMask) == prefix) atomicAdd(&cnts[w][(k >> shift) & 15], 1u);
        }
        __syncthreads();
        if (tid == 0) {
            unsigned r = sRank, cum = 0;
            for (int d = 0; d < 16; d++) {
                unsigned c = 0;
                for (int ww = 0; ww < 8; ww++) c += cnts[ww][d];
                if (cum + c > r) { sPrefix = prefix | ((unsigned)d << shift); sRank = r - cum; break; }
                cum += c;
            }
        }
        __syncthreads();
    }
    return sPrefix;
}

// same over global float array (256 threads)
__device__ unsigned radixSelectG(const float* vals, int n, unsigned rank) {
    __shared__ unsigned cnts[8][16];
    __shared__ unsigned sPrefix, sRank;
    int tid = threadIdx.x, w = tid >> 5;
    if (tid == 0) { sPrefix = 0u; sRank = rank; }
    for (int shift = 28; shift >= 0; shift -= 4) {
        if (tid < 128) ((unsigned*)cnts)[tid] = 0u;
        __syncthreads();
        unsigned prefix = sPrefix;
        unsigned hiMask = (shift == 28) ? 0u : (0xFFFFFFFFu << (shift + 4));
        for (int i = tid; i < n; i += 256) {
            unsigned k = monot(vals[i]);
            if ((k & hiMask) == prefix) atomicAdd(&cnts[w][(k >> shift) & 15], 1u);
        }
        __syncthreads();
        if (tid == 0) {
            unsigned r = sRank, cum = 0;
            for (int d = 0; d < 16; d++) {
                unsigned c = 0;
                for (int ww = 0; ww < 8; ww++) c += cnts[ww][d];
                if (cum + c > r) { sPrefix = prefix | ((unsigned)d << shift); sRank = r - cum; break; }
                cum += c;
            }
        }
        __syncthreads();
    }
    return sPrefix;
}

// masked radix select over one image of a global tensor (256 threads; fallback path)
__device__ unsigned radixSelectMaskedG(const float* src, const void* M, int base, int mode, unsigned rank) {
    __shared__ unsigned cnts[8][16];
    __shared__ unsigned sPrefix, sRank;
    int tid = threadIdx.x, w = tid >> 5;
    if (tid == 0) { sPrefix = 0u; sRank = rank; }
    for (int shift = 28; shift >= 0; shift -= 4) {
        if (tid < 128) ((unsigned*)cnts)[tid] = 0u;
        __syncthreads();
        unsigned prefix = sPrefix;
        unsigned hiMask = (shift == 28) ? 0u : (0xFFFFFFFFu << (shift + 4));
        for (int i = tid; i < HWSZ; i += 256) {
            if (!maskRT(M, base + i, mode)) continue;
            unsigned k = monot(src[base + i]);
            if ((k & hiMask) == prefix) atomicAdd(&cnts[w][(k >> shift) & 15], 1u);
        }
        __syncthreads();
        if (tid == 0) {
            unsigned r = sRank, cum = 0;
            for (int d = 0; d < 16; d++) {
                unsigned c = 0;
                for (int ww = 0; ww < 8; ww++) c += cnts[ww][d];
                if (cum + c > r) { sPrefix = prefix | ((unsigned)d << shift); sRank = r - cum; break; }
                cum += c;
            }
        }
        __syncthreads();
    }
    return sPrefix;
}

// ---------------- kernels ----------------
// k_prep: init globals + per-(img,tensor) sampling + quantile window. 128 blocks.
__global__ void __launch_bounds__(256) k_prep(const float* P, const float* Y, const void* M) {
    __shared__ unsigned skeys[SAMPN];
    __shared__ unsigned sN;
    __shared__ int sMode;
    int t = blockIdx.x, img = t >> 1, tid = threadIdx.x;
    if (tid == 0) {
        const unsigned char* b = (const unsigned char*)M;
        bool nonbin = false, offnz = false;
        for (int j = 0; j < 256; j++) {
            unsigned char v = b[j];
            if (v > 1) nonbin = true;
            if ((j & 3) && v) offnz = true;
        }
        int mode = nonbin ? 1 : (offnz ? 0 : 2);
        sMode = mode;
        if (t == 0) g_mmode = mode;
        sN = 0u;
    }
    if (tid == 1) { g_nb[t] = 0u; g_sb[t] = 0.0; g_stot[t] = 0.0; g_ccnt[t] = 0u; g_flag[t] = 0; }
    if (tid == 2 && (t & 1) == 0) { g_cnt[img] = 0u; g_rho[img] = 0.0; }
    if (t == 0 && tid >= 8 && tid < 12) {
        int s = tid - 8;
        g_gx[s] = 0.0; g_gy[s] = 0.0; g_cx[s] = 0ull; g_cy[s] = 0ull;
    }
    __syncthreads();
    int mode = sMode;
    const float* src = (t & 1) ? Y : P;
    int base = img * HWSZ;
    // 8 batches of 4 chunks for MLP
    for (int bt = 0; bt < 8; bt++) {
        float xv[4]; bool mv[4];
#pragma unroll
        for (int k = 0; k < 4; k++) {
            int idx = base + (bt * 4 + k) * SSTRIDE + tid;
            xv[k] = src[idx];
            mv[k] = maskRT(M, idx, mode);
        }
#pragma unroll
        for (int k = 0; k < 4; k++) {
            unsigned bal = __ballot_sync(0xffffffffu, mv[k]);
            if (bal) {
                int lane = tid & 31;
                unsigned pos = 0;
                int leader = __ffs(bal) - 1;
                if (lane == leader) pos = atomicAdd(&sN, (unsigned)__popc(bal));
                pos = __shfl_sync(0xffffffffu, pos, leader);
                if (mv[k]) skeys[pos + __popc(bal & ((1u << lane) - 1))] = monot(xv[k]);
            }
        }
    }
    __syncthreads();
    int n = (int)sN;
    if (n == 0) {
        if (tid == 0) { g_vlo[t] = __int_as_float(0x7f800000); g_vhi[t] = __int_as_float(0xff800000); }
        return;
    }
    unsigned rlo = (unsigned)(((long long)(n - 1) * 475) / 1000);
    unsigned rhi = (unsigned)((((long long)(n - 1) * 525) + 999) / 1000);
    if (rhi > (unsigned)(n - 1)) rhi = (unsigned)(n - 1);
    unsigned klo = radixSelectKeysSm(skeys, n, rlo);
    unsigned khi = radixSelectKeysSm(skeys, n, rhi);
    if (tid == 0) { g_vlo[t] = inv_monot(klo); g_vhi[t] = inv_monot(khi); }
}

template <int MODE>
__device__ __forceinline__ void scan_impl(const float* P, const float* Y, const void* M) {
    __shared__ float slotP[256 * SLOTS], slotY[256 * SLOTS];
    __shared__ unsigned wS[8];
    __shared__ unsigned sBP, sBY;
    __shared__ double redD[8];
    __shared__ unsigned long long redU[8];
    int img = blockIdx.y, bx = blockIdx.x, tid = threadIdx.x;
    int s = (bx * G8) >> 5;
    int e = ((bx + 1) * G8) >> 5;
    int iters = ((e - s) + 255) >> 8;
    float vloP = g_vlo[2 * img], vhiP = g_vhi[2 * img];
    float vloY = g_vlo[2 * img + 1], vhiY = g_vhi[2 * img + 1];
    const float4* P4 = (const float4*)P;
    const float4* Y4 = (const float4*)Y;
    float* myP = slotP + tid * SLOTS;
    float* myY = slotY + tid * SLOTS;
    unsigned cnt = 0, nbP = 0, nbY = 0, mcP = 0, mcY = 0;
    float sbP = 0.f, sbY = 0.f, stP = 0.f, stY = 0.f;
    for (int it = 0; it < iters; it++) {
        int g = s + it * 256 + tid;
        bool ok = g < e;
        int idx4 = img * HW4 + 2 * (ok ? g : s);
        float4 p0 = P4[idx4], p1 = P4[idx4 + 1];
        float4 q0 = Y4[idx4], q1 = Y4[idx4 + 1];
        float pv[8] = {p0.x, p0.y, p0.z, p0.w, p1.x, p1.y, p1.z, p1.w};
        float qv[8] = {q0.x, q0.y, q0.z, q0.w, q1.x, q1.y, q1.z, q1.w};
        bool mv[8];
        if (MODE == 0) {
            const unsigned* Mu = (const unsigned*)M;
            unsigned ma = Mu[idx4], mb = Mu[idx4 + 1];
#pragma unroll
            for (int j = 0; j < 4; j++) { mv[j] = (ma >> (8 * j)) & 0xffu; mv[4 + j] = (mb >> (8 * j)) & 0xffu; }
        } else {
            loadMask4<MODE>(M, idx4, mv[0], mv[1], mv[2], mv[3]);
            loadMask4<MODE>(M, idx4 + 1, mv[4], mv[5], mv[6], mv[7]);
        }
#pragma unroll
        for (int j = 0; j < 8; j++) {
            if (ok && mv[j]) {
                cnt++;
                float a = pv[j];
                stP += a;
                if (a < vloP) { nbP++; sbP += a; }
                else if (a <= vhiP) { if (mcP < SLOTS) myP[mcP] = a; mcP++; }
                float b = qv[j];
                stY += b;
                if (b < vloY) { nbY++; sbY += b; }
                else if (b <= vhiY) { if (mcY < SLOTS) myY[mcY] = b; mcY++; }
            }
        }
    }
    // tail: 4 leftover elements per image (block 31, per-thread, no collectives)
    if (bx == 31 && tid < 4) {
        int ei = img * HWSZ + G8 * 8 + tid;
        if (maskAt<MODE>(M, ei)) {
            cnt++;
            float a = P[ei];
            stP += a;
            if (a < vloP) { nbP++; sbP += a; }
            else if (a <= vhiP) { if (mcP < SLOTS) myP[mcP] = a; mcP++; }
            float b = Y[ei];
            stY += b;
            if (b < vloY) { nbY++; sbY += b; }
            else if (b <= vhiY) { if (mcY < SLOTS) myY[mcY] = b; mcY++; }
        }
    }
    int ovf = __syncthreads_or((mcP > SLOTS) | (mcY > SLOTS));
    unsigned nP = min(mcP, (unsigned)SLOTS), nY = min(mcY, (unsigned)SLOTS);
    // sums
    double r;
    r = blockReduceD<256>((double)sbP, redD); if (tid == 0) atomicAdd(&g_sb[2 * img], r); __syncthreads();
    r = blockReduceD<256>((double)sbY, redD); if (tid == 0) atomicAdd(&g_sb[2 * img + 1], r); __syncthreads();
    r = blockReduceD<256>((double)stP, redD); if (tid == 0) atomicAdd(&g_stot[2 * img], r); __syncthreads();
    r = blockReduceD<256>((double)stY, redD); if (tid == 0) atomicAdd(&g_stot[2 * img + 1], r); __syncthreads();
    unsigned long long u;
    u = blockReduceU<256>(cnt, redU); if (tid == 0) atomicAdd(&g_cnt[img], (unsigned)u); __syncthreads();
    u = blockReduceU<256>(nbP, redU); if (tid == 0) atomicAdd(&g_nb[2 * img], (unsigned)u); __syncthreads();
    u = blockReduceU<256>(nbY, redU); if (tid == 0) atomicAdd(&g_nb[2 * img + 1], (unsigned)u);
    __syncthreads();
    // packed prefix scan of (nP | nY<<16)
    int lane = tid & 31, w = tid >> 5;
    unsigned myc = nP | (nY << 16);
    unsigned inc = myc;
    for (int o = 1; o < 32; o <<= 1) {
        unsigned v2 = __shfl_up_sync(0xffffffffu, inc, o);
        if (lane >= o) inc += v2;
    }
    if (lane == 31) wS[w] = inc;
    __syncthreads();
    if (tid < 8) {
        unsigned v2 = wS[tid];
        for (int o = 1; o < 8; o <<= 1) {
            unsigned v3 = __shfl_up_sync(0xffu, v2, o);
            if (tid >= o) v2 += v3;
        }
        wS[tid] = v2;
    }
    __syncthreads();
    unsigned exc = ((w > 0) ? wS[w - 1] : 0u) + inc - myc;
    unsigned tot = wS[7];
    unsigned preP = exc & 0xffffu, preY = exc >> 16;
    unsigned totP = tot & 0xffffu, totY = tot >> 16;
    if (tid == 0) {
        sBP = atomicAdd(&g_ccnt[2 * img], totP);
        sBY = atomicAdd(&g_ccnt[2 * img + 1], totY);
        if (ovf) { g_flag[2 * img] = 1; g_flag[2 * img + 1] = 1; }
    }
    __syncthreads();
    float* candP = g_cand[2 * img];
    float* candY = g_cand[2 * img + 1];
    for (unsigned k = 0; k < nP; k++) { unsigned o = sBP + preP + k; if (o < CAP) candP[o] = myP[k]; }
    for (unsigned k = 0; k < nY; k++) { unsigned o = sBY + preY + k; if (o < CAP) candY[o] = myY[k]; }
}
__global__ void __launch_bounds__(256) k_scan(const float* P, const float* Y, const void* M) {
    int m = g_mmode;
    if (m == 0) scan_impl<0>(P, Y, M);
    else if (m == 2) scan_impl<2>(P, Y, M);
    else scan_impl<1>(P, Y, M);
}

// select (+ inline exact fallback). 128 blocks.
__global__ void __launch_bounds__(256) k_select(const float* P, const float* Y, const void* M) {
    __shared__ double redD[8];
    __shared__ unsigned long long redU[8];
    __shared__ int sFB;
    int t = blockIdx.x, img = t >> 1, tid = threadIdx.x;
    unsigned cnt = g_cnt[img];
    if (cnt == 0) { if (tid == 0) { g_med[t] = 0.f; g_isc[t] = (float)(1.0 / EPSV); } return; }
    unsigned r = (cnt - 1) >> 1;
    if (tid == 0) {
        int fb = g_flag[t];
        if (!fb) {
            unsigned nb_lo = g_nb[t];
            unsigned ncand = g_ccnt[t];
            long long j = (long long)r - (long long)nb_lo;
            if (ncand > CAP || j < 0 || j >= (long long)ncand) fb = 1;
        }
        sFB = fb;
    }
    __syncthreads();
    if (!sFB) {
        unsigned nb_lo = g_nb[t];
        unsigned ncand = g_ccnt[t];
        unsigned j = r - nb_lo;
        unsigned mkey = radixSelectG(g_cand[t], (int)ncand, j);
        unsigned nl = 0;
        double sl = 0;
        for (int i = tid; i < (int)ncand; i += 256) {
            float v = g_cand[t][i];
            if (monot(v) < mkey) { nl++; sl += (double)v; }
        }
        double sls = blockReduceD<256>(sl, redD);
        __syncthreads();
        unsigned long long nls = blockReduceU<256>(nl, redU);
        if (tid == 0) {
            double med = (double)inv_monot(mkey);
            double nb = (double)nb_lo + (double)nls;
            double Sb = g_sb[t] + sls;
            double abs_sum = g_stot[t] - 2.0 * Sb + med * (2.0 * nb - (double)cnt);
            if (abs_sum < 0.0) abs_sum = 0.0;
            double sc = abs_sum / (double)cnt + EPSV;
            g_med[t] = (float)med;
            g_isc[t] = (float)(1.0 / sc);
        }
        return;
    }
    // exact fallback: masked radix select + one stats pass
    int mode = g_mmode;
    const float* src = (t & 1) ? Y : P;
    int base = img * HWSZ;
    unsigned mkey = radixSelectMaskedG(src, M, base, mode, r);
    unsigned nb = 0;
    double Sb = 0;
    for (int i = tid; i < HWSZ; i += 256) {
        if (!maskRT(M, base + i, mode)) continue;
        float v = src[base + i];
        if (monot(v) < mkey) { nb++; Sb += (double)v; }
    }
    double sbs = blockReduceD<256>(Sb, redD);
    __syncthreads();
    unsigned long long nbs = blockReduceU<256>(nb, redU);
    if (tid == 0) {
        double med = (double)inv_monot(mkey);
        double abs_sum = g_stot[t] - 2.0 * sbs + med * (2.0 * (double)nbs - (double)cnt);
        if (abs_sum < 0.0) abs_sum = 0.0;
        double sc = abs_sum / (double)cnt + EPSV;
        g_med[t] = (float)med;
        g_isc[t] = (float)(1.0 / sc);
    }
}

template <int MODE>
__device__ __forceinline__ void main_impl(const float* P, const float* Y, const void* M) {
    __shared__ float sd[BANDSZ + WD + 4];
    __shared__ unsigned char sm[BANDSZ + WD + 4];
    __shared__ double redD[16];
    __shared__ unsigned long long redU[16];
    int img = blockIdx.y, band = blockIdx.x, tid = threadIdx.x;
    bool last = (band == NBANDS - 1);
    int nelem = last ? BANDSZ : (BANDSZ + WD);
    float medp = g_med[2 * img], medy = g_med[2 * img + 1];
    float iscp = g_isc[2 * img], iscy = g_isc[2 * img + 1];
    int ebase = img * HWSZ + band * BANDSZ;
    int base4 = ebase >> 2;
    int nv = (nelem & ~3) >> 2;
    const float4* P4 = (const float4*)P;
    const float4* Y4 = (const float4*)Y;
    for (int v = tid; v < nv; v += 512) {
        float4 p = P4[base4 + v];
        float4 q = Y4[base4 + v];
        bool m0, m1, m2, m3;
        loadMask4<MODE>(M, base4 + v, m0, m1, m2, m3);
        int o = v * 4;
        sd[o]     = (p.x - medp) * iscp - (q.x - medy) * iscy; sm[o]     = m0;
        sd[o + 1] = (p.y - medp) * iscp - (q.y - medy) * iscy; sm[o + 1] = m1;
        sd[o + 2] = (p.z - medp) * iscp - (q.z - medy) * iscy; sm[o + 2] = m2;
        sd[o + 3] = (p.w - medp) * iscp - (q.w - medy) * iscy; sm[o + 3] = m3;
    }
    if (!last && tid < 2) {   // 7770 = 1942*4 + 2 leftover
        int o = 7768 + tid;
        int gi = ebase + o;
        float p = P[gi], q = Y[gi];
        sd[o] = (p - medp) * iscp - (q - medy) * iscy;
        sm[o] = maskAt<MODE>(M, gi) ? 1 : 0;
    }
    __syncthreads();
    float rho = 0.f, gx = 0.f, gy = 0.f;
    unsigned cx = 0, cy = 0;
    int nprow = last ? 13 : 14;
    for (int i = tid; i < BANDSZ; i += 512) {
        int row = i / WD, c = i - row * WD;       // constant division -> mul/shift
        unsigned char m = sm[i];
        float d = sd[i];
        if (m) {
            rho += fabsf(d);
            if (c < WD - 1 && sm[i + 1]) { gx += fabsf(sd[i + 1] - d); cx++; }
            if (row < nprow && sm[i + WD]) { gy += fabsf(sd[i + WD] - d); cy++; }
        }
    }
    // 2x2 pool -> level 1 (7 pooled rows x 259)
    float* d1 = d1buf + img * L1SZ + band * 7 * L1W;
    unsigned char* m1 = m1buf + img * L1SZ + band * 7 * L1W;
    for (int pi = tid; pi < 7 * L1W; pi += 512) {
        int pr = pi / L1W, pc = pi - pr * L1W;
        int o0 = (2 * pr) * WD + 2 * pc;
        d1[pi] = 0.25f * (sd[o0] + sd[o0 + 1] + sd[o0 + WD] + sd[o0 + WD + 1]);
        m1[pi] = sm[o0] | sm[o0 + 1] | sm[o0 + WD] | sm[o0 + WD + 1];
    }
    double r1 = blockReduceD<512>((double)rho, redD); __syncthreads();
    double r2 = blockReduceD<512>((double)gx, redD);  __syncthreads();
    double r3 = blockReduceD<512>((double)gy, redD);  __syncthreads();
    unsigned long long u1 = blockReduceU<512>(cx, redU); __syncthreads();
    unsigned long long u2 = blockReduceU<512>(cy, redU);
    if (tid == 0) {
        atomicAdd(&g_rho[img], r1);
        atomicAdd(&g_gx[0], r2); atomicAdd(&g_gy[0], r3);
        atomicAdd(&g_cx[0], u1); atomicAdd(&g_cy[0], u2);
    }
}
__global__ void __launch_bounds__(512) k_main(const float* P, const float* Y, const void* M) {
    int m = g_mmode;
    if (m == 0) main_impl<0>(P, Y, M);
    else if (m == 2) main_impl<2>(P, Y, M);
    else main_impl<1>(P, Y, M);
}

// fused grad(level LVL) + pool(LVL -> LVL+1)
template <int LVL, int HC, int WC, int HO, int WO>
__global__ void __launch_bounds__(256) k_gp() {
    const float* d; const unsigned char* m; float* dout; unsigned char* mo;
    if (LVL == 1) { d = d1buf; m = m1buf; dout = d2buf; mo = m2buf; }
    else { d = d2buf; m = m2buf; dout = d3buf; mo = m3buf; }
    __shared__ double redD[8];
    __shared__ unsigned long long redU[8];
    constexpr int per = HC * WC;
    constexpr int total = NIMG * per;
    float gx = 0.f, gy = 0.f;
    unsigned cx = 0, cy = 0;
    for (int i = blockIdx.x * blockDim.x + threadIdx.x; i < total; i += gridDim.x * blockDim.x) {
        if (!m[i]) continue;
        int rem = i % per;
        int r = rem / WC, c = rem - r * WC;
        float dv = d[i];
        if (c < WC - 1 && m[i + 1]) { gx += fabsf(d[i + 1] - dv); cx++; }
        if (r < HC - 1 && m[i + WC]) { gy += fabsf(d[i + WC] - dv); cy++; }
    }
    constexpr int perO = HO * WO;
    constexpr int totalO = NIMG * perO;
    for (int i = blockIdx.x * blockDim.x + threadIdx.x; i < totalO; i += gridDim.x * blockDim.x) {
        int img = i / perO, rem = i - img * perO;
        int r = rem / WO, c = rem - r * WO;
        int bi = img * per + (2 * r) * WC + 2 * c;
        dout[i] = 0.25f * (d[bi] + d[bi + 1] + d[bi + WC] + d[bi + WC + 1]);
        mo[i] = m[bi] | m[bi + 1] | m[bi + WC] | m[bi + WC + 1];
    }
    double r2 = blockReduceD<256>((double)gx, redD); __syncthreads();
    double r3 = blockReduceD<256>((double)gy, redD); __syncthreads();
    unsigned long long u1 = blockReduceU<256>(cx, redU); __syncthreads();
    unsigned long long u2 = blockReduceU<256>(cy, redU);
    if (threadIdx.x == 0) {
        atomicAdd(&g_gx[LVL], r2); atomicAdd(&g_gy[LVL], r3);
        atomicAdd(&g_cx[LVL], u1); atomicAdd(&g_cy[LVL], u2);
    }
}

__global__ void __launch_bounds__(256) k_grad3() {
    const float* d = d3buf;
    const unsigned char* m = m3buf;
    __shared__ double redD[8];
    __shared__ unsigned long long redU[8];
    constexpr int per = 64 * 64;
    constexpr int total = NIMG * per;
    float gx = 0.f, gy = 0.f;
    unsigned cx = 0, cy = 0;
    for (int i = blockIdx.x * blockDim.x + threadIdx.x; i < total; i += gridDim.x * blockDim.x) {
        if (!m[i]) continue;
        int rem = i & (per - 1);
        int r = rem >> 6, c = rem & 63;
        float dv = d[i];
        if (c < 63 && m[i + 1]) { gx += fabsf(d[i + 1] - dv); cx++; }
        if (r < 63 && m[i + 64]) { gy += fabsf(d[i + 64] - dv); cy++; }
    }
    double r2 = blockReduceD<256>((double)gx, redD); __syncthreads();
    double r3 = blockReduceD<256>((double)gy, redD); __syncthreads();
    unsigned long long u1 = blockReduceU<256>(cx, redU); __syncthreads();
    unsigned long long u2 = blockReduceU<256>(cy, redU);
    if (threadIdx.x == 0) {
        atomicAdd(&g_gx[3], r2); atomicAdd(&g_gy[3], r3);
        atomicAdd(&g_cx[3], u1); atomicAdd(&g_cy[3], u2);
    }
}

__global__ void k_final(float* out) {
    if (threadIdx.x == 0 && blockIdx.x == 0) {
        double ssi = 0;
        for (int i = 0; i < NIMG; i++) {
            double v = (double)g_cnt[i];
            if (v < 1.0) v = 1.0;
            ssi += g_rho[i] / v;
        }
        ssi /= (double)NIMG;
        double g = 0;
        for (int s = 0; s < 4; s++) {
            double cx = (double)g_cx[s]; if (cx < 1.0) cx = 1.0;
            double cy = (double)g_cy[s]; if (cy < 1.0) cy = 1.0;
            g += g_gx[s] / cx + g_gy[s] / cy;
        }
        out[0] = (float)(ssi + 0.5 * (g / 4.0));
    }
}

extern "C" void kernel_launch(void* const* d_in, const int* in_sizes, int n_in,
                              void* d_out, int out_size) {
    const float* pred = (const float*)d_in[0];
    const float* yv = (const float*)d_in[1];
    const void* mask = d_in[2];
    float* out = (float*)d_out;

    k_prep<<<128, 256>>>(pred, yv, mask);
    k_scan<<<dim3(32, NIMG), 256>>>(pred, yv, mask);
    k_select<<<128, 256>>>(pred, yv, mask);
    k_main<<<dim3(NBANDS, NIMG), 512>>>(pred, yv, mask);
    k_gp<1, 259, 259, 129, 129><<<1024, 256>>>();
    k_gp<2, 129, 129, 64, 64><<<512, 256>>>();
    k_grad3<<<256, 256>>>();
    k_final<<<1, 32>>>(out);
}

// round 7
// speedup vs baseline: 3.3559x; 1.3696x over previous
#include <cuda_runtime.h>
#include <cstdint>

#define HWSZ 268324
#define HW4  67081
#define WD 518
#define NIMG 64
#define CAP 32768
#define SLOTS 12
#define EPSV 1e-8
#define SAMPN 8192
#define SSTRIDE 8385
#define BANDSZ 7252        // 14 rows * 518
#define NBANDS 37
#define L1W 259
#define L1SZ (259*259)
#define G8 33540           // full 8-element groups per image

// ---------------- static device scratch ----------------
__device__ int g_mmode;
__device__ float g_vlo[128], g_vhi[128];
__device__ int g_flag[128];
__device__ unsigned g_cnt[NIMG];
__device__ unsigned g_nb[128];
__device__ double g_sb[128];
__device__ double g_stot[128];
__device__ unsigned g_ccnt[128];
__device__ float g_cand[128][CAP];
__device__ float g_med[128], g_isc[128];
__device__ double g_rho[NIMG];
__device__ double g_gx[4], g_gy[4];
__device__ unsigned long long g_cx[4], g_cy[4];

__device__ float d1buf[NIMG * L1SZ];
__device__ unsigned char m1buf[NIMG * L1SZ];
__device__ float d2buf[NIMG * 129 * 129];
__device__ unsigned char m2buf[NIMG * 129 * 129];
__device__ float d3buf[NIMG * 64 * 64];
__device__ unsigned char m3buf[NIMG * 64 * 64];

// ---------------- helpers ----------------
__device__ __forceinline__ unsigned monot(float x) {
    unsigned u = __float_as_uint(x);
    return (u >> 31) ? ~u : (u | 0x80000000u);
}
__device__ __forceinline__ float inv_monot(unsigned k) {
    unsigned u = (k >> 31) ? (k & 0x7FFFFFFFu) : ~k;
    return __uint_as_float(u);
}
__device__ __forceinline__ bool maskRT(const void* m, int i, int mode) {
    return (mode == 0) ? ((const unsigned char*)m)[i] != 0
         : (mode == 2) ? ((const int*)m)[i] != 0
         : ((const float*)m)[i] != 0.f;
}

template <int MODE>
__device__ __forceinline__ bool maskAt(const void* m, int i) {
    if (MODE == 0) return ((const unsigned char*)m)[i] != 0;
    if (MODE == 2) return ((const int*)m)[i] != 0;
    return ((const float*)m)[i] != 0.f;
}
template <int MODE>
__device__ __forceinline__ void loadMask4(const void* m, int g4, bool& b0, bool& b1, bool& b2, bool& b3) {
    if (MODE == 0) { uchar4 v = ((const uchar4*)m)[g4]; b0 = v.x; b1 = v.y; b2 = v.z; b3 = v.w; }
    else if (MODE == 2) { int4 v = ((const int4*)m)[g4]; b0 = v.x != 0; b1 = v.y != 0; b2 = v.z != 0; b3 = v.w != 0; }
    else { float4 v = ((const float4*)m)[g4]; b0 = v.x != 0.f; b1 = v.y != 0.f; b2 = v.z != 0.f; b3 = v.w != 0.f; }
}

template <int NT>
__device__ __forceinline__ double blockReduceD(double v, double* sh) {
    constexpr int NW = NT / 32;
    for (int o = 16; o; o >>= 1) v += __shfl_down_sync(0xffffffffu, v, o);
    int w = threadIdx.x >> 5, l = threadIdx.x & 31;
    if (l == 0) sh[w] = v;
    __syncthreads();
    double r = 0;
    if (threadIdx.x < NW) {
        r = sh[threadIdx.x];
        for (int o = NW / 2; o; o >>= 1) r += __shfl_down_sync((unsigned)((1ull << NW) - 1), r, o);
    }
    return r;
}
template <int NT>
__device__ __forceinline__ unsigned long long blockReduceU(unsigned long long v, unsigned long long* sh) {
    constexpr int NW = NT / 32;
    for (int o = 16; o; o >>= 1) v += __shfl_down_sync(0xffffffffu, v, o);
    int w = threadIdx.x >> 5, l = threadIdx.x & 31;
    if (l == 0) sh[w] = v;
    __syncthreads();
    unsigned long long r = 0;
    if (threadIdx.x < NW) {
        r = sh[threadIdx.x];
        for (int o = NW / 2; o; o >>= 1) r += __shfl_down_sync((unsigned)((1ull << NW) - 1), r, o);
    }
    return r;
}

// 4-bit radix select over smem monot keys. Block-collective (256 threads).
__device__ unsigned radixSelectKeysSm(const unsigned* keys, int n, unsigned rank) {
    __shared__ unsigned cnts[8][16];
    __shared__ unsigned sPrefix, sRank;
    int tid = threadIdx.x, w = tid >> 5;
    if (tid == 0) { sPrefix = 0u; sRank = rank; }
    for (int shift = 28; shift >= 0; shift -= 4) {
        if (tid < 128) ((unsigned*)cnts)[tid] = 0u;
        __syncthreads();
        unsigned prefix = sPrefix;
        unsigned hiMask = (shift == 28) ? 0u : (0xFFFFFFFFu << (shift + 4));
        for (int i = tid; i < n; i += 256) {
            unsigned k = keys[i];
            if ((k & hiMask) == prefix) atomicAdd(&cnts[w][(k >> shift) & 15], 1u);
        }
        __syncthreads();
        if (tid == 0) {
            unsigned r = sRank, cum = 0;
            for (int d = 0; d < 16; d++) {
                unsigned c = 0;
                for (int ww = 0; ww < 8; ww++) c += cnts[ww][d];
                if (cum + c > r) { sPrefix = prefix | ((unsigned)d << shift); sRank = r - cum; break; }
                cum += c;
            }
        }
        __syncthreads();
    }
    return sPrefix;
}

// same over global float array (256 threads)
__device__ unsigned radixSelectG(const float* vals, int n, unsigned rank) {
    __shared__ unsigned cnts[8][16];
    __shared__ unsigned sPrefix, sRank;
    int tid = threadIdx.x, w = tid >> 5;
    if (tid == 0) { sPrefix = 0u; sRank = rank; }
    for (int shift = 28; shift >= 0; shift -= 4) {
        if (tid < 128) ((unsigned*)cnts)[tid] = 0u;
        __syncthreads();
        unsigned prefix = sPrefix;
        unsigned hiMask = (shift == 28) ? 0u : (0xFFFFFFFFu << (shift + 4));
        for (int i = tid; i < n; i += 256) {
            unsigned k = monot(vals[i]);
            if ((k & hiMask) == prefix) atomicAdd(&cnts[w][(k >> shift) & 15], 1u);
        }
        __syncthreads();
        if (tid == 0) {
            unsigned r = sRank, cum = 0;
            for (int d = 0; d < 16; d++) {
                unsigned c = 0;
                for (int ww = 0; ww < 8; ww++) c += cnts[ww][d];
                if (cum + c > r) { sPrefix = prefix | ((unsigned)d << shift); sRank = r - cum; break; }
                cum += c;
            }
        }
        __syncthreads();
    }
    return sPrefix;
}

// masked radix select over one image of a global tensor (256 threads; fallback path)
__device__ unsigned radixSelectMaskedG(const float* src, const void* M, int base, int mode, unsigned rank) {
    __shared__ unsigned cnts[8][16];
    __shared__ unsigned sPrefix, sRank;
    int tid = threadIdx.x, w = tid >> 5;
    if (tid == 0) { sPrefix = 0u; sRank = rank; }
    for (int shift = 28; shift >= 0; shift -= 4) {
        if (tid < 128) ((unsigned*)cnts)[tid] = 0u;
        __syncthreads();
        unsigned prefix = sPrefix;
        unsigned hiMask = (shift == 28) ? 0u : (0xFFFFFFFFu << (shift + 4));
        for (int i = tid; i < HWSZ; i += 256) {
            if (!maskRT(M, base + i, mode)) continue;
            unsigned k = monot(src[base + i]);
            if ((k & hiMask) == prefix) atomicAdd(&cnts[w][(k >> shift) & 15], 1u);
        }
        __syncthreads();
        if (tid == 0) {
            unsigned r = sRank, cum = 0;
            for (int d = 0; d < 16; d++) {
                unsigned c = 0;
                for (int ww = 0; ww < 8; ww++) c += cnts[ww][d];
                if (cum + c > r) { sPrefix = prefix | ((unsigned)d << shift); sRank = r - cum; break; }
                cum += c;
            }
        }
        __syncthreads();
    }
    return sPrefix;
}

// ---------------- kernels ----------------
// k_prep: init globals + per-(img,tensor) sampling + quantile window. 128 blocks.
__global__ void __launch_bounds__(256) k_prep(const float* P, const float* Y, const void* M) {
    __shared__ unsigned skeys[SAMPN];
    __shared__ unsigned sN;
    __shared__ int sMode;
    int t = blockIdx.x, img = t >> 1, tid = threadIdx.x;
    if (tid == 0) {
        const unsigned char* b = (const unsigned char*)M;
        bool nonbin = false, offnz = false;
        for (int j = 0; j < 256; j++) {
            unsigned char v = b[j];
            if (v > 1) nonbin = true;
            if ((j & 3) && v) offnz = true;
        }
        int mode = nonbin ? 1 : (offnz ? 0 : 2);
        sMode = mode;
        if (t == 0) g_mmode = mode;
        sN = 0u;
    }
    if (tid == 1) { g_nb[t] = 0u; g_sb[t] = 0.0; g_stot[t] = 0.0; g_ccnt[t] = 0u; g_flag[t] = 0; }
    if (tid == 2 && (t & 1) == 0) { g_cnt[img] = 0u; g_rho[img] = 0.0; }
    if (t == 0 && tid >= 8 && tid < 12) {
        int s = tid - 8;
        g_gx[s] = 0.0; g_gy[s] = 0.0; g_cx[s] = 0ull; g_cy[s] = 0ull;
    }
    __syncthreads();
    int mode = sMode;
    const float* src = (t & 1) ? Y : P;
    int base = img * HWSZ;
    for (int bt = 0; bt < 8; bt++) {
        float xv[4]; bool mv[4];
#pragma unroll
        for (int k = 0; k < 4; k++) {
            int idx = base + (bt * 4 + k) * SSTRIDE + tid;
            xv[k] = src[idx];
            mv[k] = maskRT(M, idx, mode);
        }
#pragma unroll
        for (int k = 0; k < 4; k++) {
            unsigned bal = __ballot_sync(0xffffffffu, mv[k]);
            if (bal) {
                int lane = tid & 31;
                unsigned pos = 0;
                int leader = __ffs(bal) - 1;
                if (lane == leader) pos = atomicAdd(&sN, (unsigned)__popc(bal));
                pos = __shfl_sync(0xffffffffu, pos, leader);
                if (mv[k]) skeys[pos + __popc(bal & ((1u << lane) - 1))] = monot(xv[k]);
            }
        }
    }
    __syncthreads();
    int n = (int)sN;
    if (n == 0) {
        if (tid == 0) { g_vlo[t] = __int_as_float(0x7f800000); g_vhi[t] = __int_as_float(0xff800000); }
        return;
    }
    unsigned rlo = (unsigned)(((long long)(n - 1) * 475) / 1000);
    unsigned rhi = (unsigned)((((long long)(n - 1) * 525) + 999) / 1000);
    if (rhi > (unsigned)(n - 1)) rhi = (unsigned)(n - 1);
    unsigned klo = radixSelectKeysSm(skeys, n, rlo);
    unsigned khi = radixSelectKeysSm(skeys, n, rhi);
    if (tid == 0) { g_vlo[t] = inv_monot(klo); g_vhi[t] = inv_monot(khi); }
}

struct ScanShared {
    float slotP[256 * SLOTS];
    float slotY[256 * SLOTS];
    unsigned wS[8];
    unsigned sBP, sBY;
    double redD[8];
    unsigned long long redU[8];
};

template <int MODE>
__device__ __forceinline__ void scan_impl(const float* P, const float* Y, const void* M, ScanShared* sh) {
    int img = blockIdx.y, bx = blockIdx.x, tid = threadIdx.x;
    int s = (bx * G8) >> 5;
    int e = ((bx + 1) * G8) >> 5;
    int iters = ((e - s) + 255) >> 8;
    float vloP = g_vlo[2 * img], vhiP = g_vhi[2 * img];
    float vloY = g_vlo[2 * img + 1], vhiY = g_vhi[2 * img + 1];
    const float4* P4 = (const float4*)P;
    const float4* Y4 = (const float4*)Y;
    float* myP = sh->slotP + tid * SLOTS;
    float* myY = sh->slotY + tid * SLOTS;
    unsigned cnt = 0, nbP = 0, nbY = 0, mcP = 0, mcY = 0;
    float sbP = 0.f, sbY = 0.f, stP = 0.f, stY = 0.f;
    for (int it = 0; it < iters; it++) {
        int g = s + it * 256 + tid;
        bool ok = g < e;
        int idx4 = img * HW4 + 2 * (ok ? g : s);
        float4 p0 = P4[idx4], p1 = P4[idx4 + 1];
        float4 q0 = Y4[idx4], q1 = Y4[idx4 + 1];
        float pv[8] = {p0.x, p0.y, p0.z, p0.w, p1.x, p1.y, p1.z, p1.w};
        float qv[8] = {q0.x, q0.y, q0.z, q0.w, q1.x, q1.y, q1.z, q1.w};
        bool mv[8];
        if (MODE == 0) {
            const unsigned* Mu = (const unsigned*)M;
            unsigned ma = Mu[idx4], mb = Mu[idx4 + 1];
#pragma unroll
            for (int j = 0; j < 4; j++) { mv[j] = (ma >> (8 * j)) & 0xffu; mv[4 + j] = (mb >> (8 * j)) & 0xffu; }
        } else {
            loadMask4<MODE>(M, idx4, mv[0], mv[1], mv[2], mv[3]);
            loadMask4<MODE>(M, idx4 + 1, mv[4], mv[5], mv[6], mv[7]);
        }
#pragma unroll
        for (int j = 0; j < 8; j++) {
            if (ok && mv[j]) {
                cnt++;
                float a = pv[j];
                stP += a;
                if (a < vloP) { nbP++; sbP += a; }
                else if (a <= vhiP) { if (mcP < SLOTS) myP[mcP] = a; mcP++; }
                float b = qv[j];
                stY += b;
                if (b < vloY) { nbY++; sbY += b; }
                else if (b <= vhiY) { if (mcY < SLOTS) myY[mcY] = b; mcY++; }
            }
        }
    }
    // tail: 4 leftover elements per image (block 31, per-thread, no collectives)
    if (bx == 31 && tid < 4) {
        int ei = img * HWSZ + G8 * 8 + tid;
        if (maskAt<MODE>(M, ei)) {
            cnt++;
            float a = P[ei];
            stP += a;
            if (a < vloP) { nbP++; sbP += a; }
            else if (a <= vhiP) { if (mcP < SLOTS) myP[mcP] = a; mcP++; }
            float b = Y[ei];
            stY += b;
            if (b < vloY) { nbY++; sbY += b; }
            else if (b <= vhiY) { if (mcY < SLOTS) myY[mcY] = b; mcY++; }
        }
    }
    int ovf = __syncthreads_or((mcP > SLOTS) | (mcY > SLOTS));
    unsigned nP = min(mcP, (unsigned)SLOTS), nY = min(mcY, (unsigned)SLOTS);
    double r;
    r = blockReduceD<256>((double)sbP, sh->redD); if (tid == 0) atomicAdd(&g_sb[2 * img], r); __syncthreads();
    r = blockReduceD<256>((double)sbY, sh->redD); if (tid == 0) atomicAdd(&g_sb[2 * img + 1], r); __syncthreads();
    r = blockReduceD<256>((double)stP, sh->redD); if (tid == 0) atomicAdd(&g_stot[2 * img], r); __syncthreads();
    r = blockReduceD<256>((double)stY, sh->redD); if (tid == 0) atomicAdd(&g_stot[2 * img + 1], r); __syncthreads();
    unsigned long long u;
    u = blockReduceU<256>(cnt, sh->redU); if (tid == 0) atomicAdd(&g_cnt[img], (unsigned)u); __syncthreads();
    u = blockReduceU<256>(nbP, sh->redU); if (tid == 0) atomicAdd(&g_nb[2 * img], (unsigned)u); __syncthreads();
    u = blockReduceU<256>(nbY, sh->redU); if (tid == 0) atomicAdd(&g_nb[2 * img + 1], (unsigned)u);
    __syncthreads();
    // packed prefix scan of (nP | nY<<16)
    int lane = tid & 31, w = tid >> 5;
    unsigned myc = nP | (nY << 16);
    unsigned inc = myc;
    for (int o = 1; o < 32; o <<= 1) {
        unsigned v2 = __shfl_up_sync(0xffffffffu, inc, o);
        if (lane >= o) inc += v2;
    }
    if (lane == 31) sh->wS[w] = inc;
    __syncthreads();
    if (tid < 8) {
        unsigned v2 = sh->wS[tid];
        for (int o = 1; o < 8; o <<= 1) {
            unsigned v3 = __shfl_up_sync(0xffu, v2, o);
            if (tid >= o) v2 += v3;
        }
        sh->wS[tid] = v2;
    }
    __syncthreads();
    unsigned exc = ((w > 0) ? sh->wS[w - 1] : 0u) + inc - myc;
    unsigned tot = sh->wS[7];
    unsigned preP = exc & 0xffffu, preY = exc >> 16;
    unsigned totP = tot & 0xffffu, totY = tot >> 16;
    if (tid == 0) {
        sh->sBP = atomicAdd(&g_ccnt[2 * img], totP);
        sh->sBY = atomicAdd(&g_ccnt[2 * img + 1], totY);
        if (ovf) { g_flag[2 * img] = 1; g_flag[2 * img + 1] = 1; }
    }
    __syncthreads();
    float* candP = g_cand[2 * img];
    float* candY = g_cand[2 * img + 1];
    for (unsigned k = 0; k < nP; k++) { unsigned o = sh->sBP + preP + k; if (o < CAP) candP[o] = myP[k]; }
    for (unsigned k = 0; k < nY; k++) { unsigned o = sh->sBY + preY + k; if (o < CAP) candY[o] = myY[k]; }
}
__global__ void __launch_bounds__(256) k_scan(const float* P, const float* Y, const void* M) {
    __shared__ ScanShared sh;    // single instance shared across instantiations
    int m = g_mmode;
    if (m == 0) scan_impl<0>(P, Y, M, &sh);
    else if (m == 2) scan_impl<2>(P, Y, M, &sh);
    else scan_impl<1>(P, Y, M, &sh);
}

// select (+ inline exact fallback). 128 blocks.
__global__ void __launch_bounds__(256) k_select(const float* P, const float* Y, const void* M) {
    __shared__ double redD[8];
    __shared__ unsigned long long redU[8];
    __shared__ int sFB;
    int t = blockIdx.x, img = t >> 1, tid = threadIdx.x;
    unsigned cnt = g_cnt[img];
    if (cnt == 0) { if (tid == 0) { g_med[t] = 0.f; g_isc[t] = (float)(1.0 / EPSV); } return; }
    unsigned r = (cnt - 1) >> 1;
    if (tid == 0) {
        int fb = g_flag[t];
        if (!fb) {
            unsigned nb_lo = g_nb[t];
            unsigned ncand = g_ccnt[t];
            long long j = (long long)r - (long long)nb_lo;
            if (ncand > CAP || j < 0 || j >= (long long)ncand) fb = 1;
        }
        sFB = fb;
    }
    __syncthreads();
    if (!sFB) {
        unsigned nb_lo = g_nb[t];
        unsigned ncand = g_ccnt[t];
        unsigned j = r - nb_lo;
        unsigned mkey = radixSelectG(g_cand[t], (int)ncand, j);
        unsigned nl = 0;
        double sl = 0;
        for (int i = tid; i < (int)ncand; i += 256) {
            float v = g_cand[t][i];
            if (monot(v) < mkey) { nl++; sl += (double)v; }
        }
        double sls = blockReduceD<256>(sl, redD);
        __syncthreads();
        unsigned long long nls = blockReduceU<256>(nl, redU);
        if (tid == 0) {
            double med = (double)inv_monot(mkey);
            double nb = (double)nb_lo + (double)nls;
            double Sb = g_sb[t] + sls;
            double abs_sum = g_stot[t] - 2.0 * Sb + med * (2.0 * nb - (double)cnt);
            if (abs_sum < 0.0) abs_sum = 0.0;
            double sc = abs_sum / (double)cnt + EPSV;
            g_med[t] = (float)med;
            g_isc[t] = (float)(1.0 / sc);
        }
        return;
    }
    // exact fallback: masked radix select + one stats pass
    int mode = g_mmode;
    const float* src = (t & 1) ? Y : P;
    int base = img * HWSZ;
    unsigned mkey = radixSelectMaskedG(src, M, base, mode, r);
    unsigned nb = 0;
    double Sb = 0;
    for (int i = tid; i < HWSZ; i += 256) {
        if (!maskRT(M, base + i, mode)) continue;
        float v = src[base + i];
        if (monot(v) < mkey) { nb++; Sb += (double)v; }
    }
    double sbs = blockReduceD<256>(Sb, redD);
    __syncthreads();
    unsigned long long nbs = blockReduceU<256>(nb, redU);
    if (tid == 0) {
        double med = (double)inv_monot(mkey);
        double abs_sum = g_stot[t] - 2.0 * sbs + med * (2.0 * (double)nbs - (double)cnt);
        if (abs_sum < 0.0) abs_sum = 0.0;
        double sc = abs_sum / (double)cnt + EPSV;
        g_med[t] = (float)med;
        g_isc[t] = (float)(1.0 / sc);
    }
}

struct MainShared {
    float sd[BANDSZ + WD + 4];
    unsigned char sm[BANDSZ + WD + 4];
    double redD[16];
    unsigned long long redU[16];
};

template <int MODE>
__device__ __forceinline__ void main_impl(const float* P, const float* Y, const void* M, MainShared* sh) {
    float* sd = sh->sd;
    unsigned char* sm = sh->sm;
    int img = blockIdx.y, band = blockIdx.x, tid = threadIdx.x;
    bool last = (band == NBANDS - 1);
    int nelem = last ? BANDSZ : (BANDSZ + WD);
    float medp = g_med[2 * img], medy = g_med[2 * img + 1];
    float iscp = g_isc[2 * img], iscy = g_isc[2 * img + 1];
    int ebase = img * HWSZ + band * BANDSZ;
    int base4 = ebase >> 2;
    int nv = (nelem & ~3) >> 2;
    const float4* P4 = (const float4*)P;
    const float4* Y4 = (const float4*)Y;
    for (int v = tid; v < nv; v += 512) {
        float4 p = P4[base4 + v];
        float4 q = Y4[base4 + v];
        bool m0, m1, m2, m3;
        loadMask4<MODE>(M, base4 + v, m0, m1, m2, m3);
        int o = v * 4;
        sd[o]     = (p.x - medp) * iscp - (q.x - medy) * iscy; sm[o]     = m0;
        sd[o + 1] = (p.y - medp) * iscp - (q.y - medy) * iscy; sm[o + 1] = m1;
        sd[o + 2] = (p.z - medp) * iscp - (q.z - medy) * iscy; sm[o + 2] = m2;
        sd[o + 3] = (p.w - medp) * iscp - (q.w - medy) * iscy; sm[o + 3] = m3;
    }
    if (!last && tid < 2) {   // 7770 = 1942*4 + 2 leftover
        int o = 7768 + tid;
        int gi = ebase + o;
        float p = P[gi], q = Y[gi];
        sd[o] = (p - medp) * iscp - (q - medy) * iscy;
        sm[o] = maskAt<MODE>(M, gi) ? 1 : 0;
    }
    __syncthreads();
    float rho = 0.f, gx = 0.f, gy = 0.f;
    unsigned cx = 0, cy = 0;
    int nprow = last ? 13 : 14;
    for (int i = tid; i < BANDSZ; i += 512) {
        int row = i / WD, c = i - row * WD;       // constant division -> mul/shift
        unsigned char m = sm[i];
        float d = sd[i];
        if (m) {
            rho += fabsf(d);
            if (c < WD - 1 && sm[i + 1]) { gx += fabsf(sd[i + 1] - d); cx++; }
            if (row < nprow && sm[i + WD]) { gy += fabsf(sd[i + WD] - d); cy++; }
        }
    }
    // 2x2 pool -> level 1 (7 pooled rows x 259)
    float* d1 = d1buf + img * L1SZ + band * 7 * L1W;
    unsigned char* m1 = m1buf + img * L1SZ + band * 7 * L1W;
    for (int pi = tid; pi < 7 * L1W; pi += 512) {
        int pr = pi / L1W, pc = pi - pr * L1W;
        int o0 = (2 * pr) * WD + 2 * pc;
        d1[pi] = 0.25f * (sd[o0] + sd[o0 + 1] + sd[o0 + WD] + sd[o0 + WD + 1]);
        m1[pi] = sm[o0] | sm[o0 + 1] | sm[o0 + WD] | sm[o0 + WD + 1];
    }
    double r1 = blockReduceD<512>((double)rho, sh->redD); __syncthreads();
    double r2 = blockReduceD<512>((double)gx, sh->redD);  __syncthreads();
    double r3 = blockReduceD<512>((double)gy, sh->redD);  __syncthreads();
    unsigned long long u1 = blockReduceU<512>(cx, sh->redU); __syncthreads();
    unsigned long long u2 = blockReduceU<512>(cy, sh->redU);
    if (tid == 0) {
        atomicAdd(&g_rho[img], r1);
        atomicAdd(&g_gx[0], r2); atomicAdd(&g_gy[0], r3);
        atomicAdd(&g_cx[0], u1); atomicAdd(&g_cy[0], u2);
    }
}
__global__ void __launch_bounds__(512) k_main(const float* P, const float* Y, const void* M) {
    __shared__ MainShared sh;    // single instance shared across instantiations
    int m = g_mmode;
    if (m == 0) main_impl<0>(P, Y, M, &sh);
    else if (m == 2) main_impl<2>(P, Y, M, &sh);
    else main_impl<1>(P, Y, M, &sh);
}

// fused grad(level LVL) + pool(LVL -> LVL+1)
template <int LVL, int HC, int WC, int HO, int WO>
__global__ void __launch_bounds__(256) k_gp() {
    const float* d; const unsigned char* m; float* dout; unsigned char* mo;
    if (LVL == 1) { d = d1buf; m = m1buf; dout = d2buf; mo = m2buf; }
    else { d = d2buf; m = m2buf; dout = d3buf; mo = m3buf; }
    __shared__ double redD[8];
    __shared__ unsigned long long redU[8];
    constexpr int per = HC * WC;
    constexpr int total = NIMG * per;
    float gx = 0.f, gy = 0.f;
    unsigned cx = 0, cy = 0;
    for (int i = blockIdx.x * blockDim.x + threadIdx.x; i < total; i += gridDim.x * blockDim.x) {
        if (!m[i]) continue;
        int rem = i % per;
        int r = rem / WC, c = rem - r * WC;
        float dv = d[i];
        if (c < WC - 1 && m[i + 1]) { gx += fabsf(d[i + 1] - dv); cx++; }
        if (r < HC - 1 && m[i + WC]) { gy += fabsf(d[i + WC] - dv); cy++; }
    }
    constexpr int perO = HO * WO;
    constexpr int totalO = NIMG * perO;
    for (int i = blockIdx.x * blockDim.x + threadIdx.x; i < totalO; i += gridDim.x * blockDim.x) {
        int img = i / perO, rem = i - img * perO;
        int r = rem / WO, c = rem - r * WO;
        int bi = img * per + (2 * r) * WC + 2 * c;
        dout[i] = 0.25f * (d[bi] + d[bi + 1] + d[bi + WC] + d[bi + WC + 1]);
        mo[i] = m[bi] | m[bi + 1] | m[bi + WC] | m[bi + WC + 1];
    }
    double r2 = blockReduceD<256>((double)gx, redD); __syncthreads();
    double r3 = blockReduceD<256>((double)gy, redD); __syncthreads();
    unsigned long long u1 = blockReduceU<256>(cx, redU); __syncthreads();
    unsigned long long u2 = blockReduceU<256>(cy, redU);
    if (threadIdx.x == 0) {
        atomicAdd(&g_gx[LVL], r2); atomicAdd(&g_gy[LVL], r3);
        atomicAdd(&g_cx[LVL], u1); atomicAdd(&g_cy[LVL], u2);
    }
}

__global__ void __launch_bounds__(256) k_grad3() {
    const float* d = d3buf;
    const unsigned char* m = m3buf;
    __shared__ double redD[8];
    __shared__ unsigned long long redU[8];
    constexpr int per = 64 * 64;
    constexpr int total = NIMG * per;
    float gx = 0.f, gy = 0.f;
    unsigned cx = 0, cy = 0;
    for (int i = blockIdx.x * blockDim.x + threadIdx.x; i < total; i += gridDim.x * blockDim.x) {
        if (!m[i]) continue;
        int rem = i & (per - 1);
        int r = rem >> 6, c = rem & 63;
        float dv = d[i];
        if (c < 63 && m[i + 1]) { gx += fabsf(d[i + 1] - dv); cx++; }
        if (r < 63 && m[i + 64]) { gy += fabsf(d[i + 64] - dv); cy++; }
    }
    double r2 = blockReduceD<256>((double)gx, redD); __syncthreads();
    double r3 = blockReduceD<256>((double)gy, redD); __syncthreads();
    unsigned long long u1 = blockReduceU<256>(cx, redU); __syncthreads();
    unsigned long long u2 = blockReduceU<256>(cy, redU);
    if (threadIdx.x == 0) {
        atomicAdd(&g_gx[3], r2); atomicAdd(&g_gy[3], r3);
        atomicAdd(&g_cx[3], u1); atomicAdd(&g_cy[3], u2);
    }
}

__global__ void k_final(float* out) {
    if (threadIdx.x == 0 && blockIdx.x == 0) {
        double ssi = 0;
        for (int i = 0; i < NIMG; i++) {
            double v = (double)g_cnt[i];
            if (v < 1.0) v = 1.0;
            ssi += g_rho[i] / v;
        }
        ssi /= (double)NIMG;
        double g = 0;
        for (int s = 0; s < 4; s++) {
            double cx = (double)g_cx[s]; if (cx < 1.0) cx = 1.0;
            double cy = (double)g_cy[s]; if (cy < 1.0) cy = 1.0;
            g += g_gx[s] / cx + g_gy[s] / cy;
        }
        out[0] = (float)(ssi + 0.5 * (g / 4.0));
    }
}

extern "C" void kernel_launch(void* const* d_in, const int* in_sizes, int n_in,
                              void* d_out, int out_size) {
    const float* pred = (const float*)d_in[0];
    const float* yv = (const float*)d_in[1];
    const void* mask = d_in[2];
    float* out = (float*)d_out;

    k_prep<<<128, 256>>>(pred, yv, mask);
    k_scan<<<dim3(32, NIMG), 256>>>(pred, yv, mask);
    k_select<<<128, 256>>>(pred, yv, mask);
    k_main<<<dim3(NBANDS, NIMG), 512>>>(pred, yv, mask);
    k_gp<1, 259, 259, 129, 129><<<1024, 256>>>();
    k_gp<2, 129, 129, 64, 64><<<512, 256>>>();
    k_grad3<<<256, 256>>>();
    k_final<<<1, 32>>>(out);
}